// round 14
// baseline (speedup 1.0000x reference)
#include <cuda_runtime.h>
#include <cuda_bf16.h>
#include <math.h>

// ---------------------------------------------------------------------------
// Problem constants
// ---------------------------------------------------------------------------
constexpr int Bq = 8, Lq = 12, Nn = 207, Dm = 512, Hh = 8, Ff = 2048;
constexpr int Ol = 12, NGc = 3;
constexpr int T  = Lq * Nn;          // 2484
constexpr int MT = Bq * T;           // 19872 rows
constexpr int E  = Dm / Hh;          // 64
constexpr int CC = Dm * (NGc + 1) * 2 + Dm;  // 4608
constexpr int NP = 224;              // padded N/K for graph stage (mult of 32)
constexpr int KVS = 12;              // kv split factor (T = 12 * 207 exactly)
constexpr int TCH = T / KVS;         // 207
constexpr int KSPL = 3584;           // GCN chunk1 end (slices 0-6)
constexpr int KSP2 = 4096;           // GCN chunk7 end (slice 7)

constexpr size_t MTD = (size_t)MT * Dm;

// ---- scratch set 1 (encoder chain) + shared tensors
constexpr size_t OFF_XR   = 0;
constexpr size_t OFF_STR  = 1 * MTD;
constexpr size_t OFF_Q    = 2 * MTD;
constexpr size_t OFF_K    = 3 * MTD;
constexpr size_t OFF_V    = 4 * MTD;
constexpr size_t OFF_ATTN = 5 * MTD;
constexpr size_t OFF_H    = 6 * MTD;
constexpr size_t OFF_Y    = 7 * MTD;
constexpr size_t OFF_YR   = 8 * MTD;
constexpr size_t OFF_MEM  = 9 * MTD;
constexpr size_t OFF_MEMR = 10 * MTD;
constexpr size_t OFF_SOUT = 11 * MTD;
constexpr size_t OFF_SOUTR= 12 * MTD;
constexpr size_t OFF_FFN  = 13 * MTD;                 // 4*MTD
constexpr size_t OFF_WEQ  = 17 * MTD;
constexpr size_t SZ_W4    = (size_t)4 * Dm * Dm;
constexpr size_t OFF_WDS  = OFF_WEQ + SZ_W4;
constexpr size_t OFF_WDC  = OFF_WDS + SZ_W4;
constexpr size_t OFF_WE1  = OFF_WDC + SZ_W4;
constexpr size_t SZ_WF    = (size_t)Dm * Ff;
constexpr size_t OFF_WE2  = OFF_WE1 + SZ_WF;
constexpr size_t OFF_WD1  = OFF_WE2 + SZ_WF;
constexpr size_t OFF_WD2  = OFF_WD1 + SZ_WF;
constexpr size_t OFF_WG   = OFF_WD2 + SZ_WF;
constexpr size_t SZ_WG    = (size_t)Ol * Dm * CC;
constexpr size_t OFF_TSWT = OFF_WG + SZ_WG;
constexpr size_t OFF_ADJ  = OFF_TSWT + (size_t)Dm * NP;
constexpr size_t OFF_SCALE= OFF_ADJ + (size_t)NGc * NP * NP;
constexpr size_t OFF_SHIFT= OFF_SCALE + (size_t)Ol * Dm;
constexpr size_t OFF_KVP  = OFF_SHIFT + (size_t)Ol * Dm;
constexpr size_t OFF_KSP  = OFF_KVP + (size_t)KVS * 64 * E * E;
constexpr size_t OFF_KV   = OFF_KSP + (size_t)KVS * 64 * E;
constexpr size_t OFF_KSUM = OFF_KV + (size_t)64 * E * E;
constexpr size_t OFF_S2   = OFF_KSUM + (size_t)64 * E;
constexpr size_t OFF_CAT  = OFF_S2 + (size_t)MT * NP;
// ---- scratch set 2 (decoder chain)
constexpr size_t OFF_Q2   = OFF_CAT + (size_t)Bq * Ol * CC * NP;
constexpr size_t OFF_K2   = OFF_Q2 + MTD;
constexpr size_t OFF_V2   = OFF_K2 + MTD;
constexpr size_t OFF_ATTN2= OFF_V2 + MTD;
constexpr size_t OFF_H2   = OFF_ATTN2 + MTD;
constexpr size_t OFF_Y2   = OFF_H2 + MTD;
constexpr size_t OFF_YR2  = OFF_Y2 + MTD;
constexpr size_t OFF_FFN2 = OFF_YR2 + MTD;
constexpr size_t OFF_KVP2 = OFF_FFN2 + 4 * MTD;
constexpr size_t OFF_KSP2 = OFF_KVP2 + (size_t)KVS * 64 * E * E;
constexpr size_t OFF_KV2  = OFF_KSP2 + (size_t)KVS * 64 * E;
constexpr size_t OFF_KSUM2= OFF_KV2 + (size_t)64 * E * E;
// ---- GCN partial scratch, [n][m] layout: 96 x NP x Dm
constexpr size_t OFF_GS   = OFF_KSUM2 + (size_t)64 * E;
constexpr size_t SZ_GS1   = (size_t)NP * Dm;
constexpr size_t TOTAL    = OFF_GS + (size_t)Bq * Ol * SZ_GS1 + 4096;

__device__ __align__(16) float g_buf[TOTAL];

__device__ __forceinline__ unsigned f2tf(float x) {
    unsigned r;
    asm("cvt.rna.tf32.f32 %0, %1;" : "=r"(r) : "f"(x));
    return r;
}
__device__ __forceinline__ float rtf(float x) { return __uint_as_float(f2tf(x)); }
__device__ __forceinline__ unsigned fbits(float x) { return __float_as_uint(x); }

// ---------------------------------------------------------------------------
// TF32 tensor-core batched GEMM, cp.async 3-stage pipeline, BK=32 (R11 core).
// EPI: 0 none | 1 +bias[n] | 2 +bias[n],elu+1 | 3 +bias[n],gelu(tanh)
//      4 +bias[n]+res[m,n] | 5 legacy transposed affine store
//      6 +bias[n], elu+1 only when bz < eluN
//      7 smem-transpose: v += P3[n*Dm+m]; v=v*P1[m]+P2[m]; coalesced C[n*ldc+m]
//      8 smem-transpose: raw partials, coalesced store C[n*ldc+m]
//      9 smem-transpose: v += P3[n*Dm+m]; raw store (mid-chunk accumulate)
// ---------------------------------------------------------------------------
constexpr int STAGES = 3;
constexpr int BK   = 32;
constexpr int ASTR = 36;
constexpr int BSTR = 136;
constexpr int ASZ  = 128 * ASTR;
constexpr int BSZ  = BK * BSTR;
constexpr size_t GSMEM = (size_t)STAGES * (ASZ + BSZ) * 4;   // 107520 B
constexpr int TSTR = 133;

template <int EPI, bool RND>
__global__ void __launch_bounds__(256, 2)
gemm_k(const float* __restrict__ A, int lda, size_t sA_, int mA, size_t sA2,
       const float* __restrict__ Bm, int ldb, size_t sB_, int mB, int dB,
       float* __restrict__ C, int ldc, size_t sC, int mC, size_t sC2,
       const float* __restrict__ P1, size_t sP1, int mP1,
       const float* __restrict__ P2, size_t sP2, int mP2,
       const float* __restrict__ P3, size_t sP3,
       int M, int N, int K, int KB, int eluN)
{
    extern __shared__ float smem[];
    float* sA = smem;
    float* sB = smem + (size_t)STAGES * ASZ;

    int bz = blockIdx.z;
    A  += (size_t)(bz % mA) * sA_ + (size_t)(bz / mA) * sA2;
    Bm += (size_t)((bz / dB) % mB) * sB_;
    C  += (size_t)(bz % mC) * sC + (size_t)(bz / mC) * sC2;
    const float* p1 = (EPI > 0) ? P1 + (size_t)(bz % mP1) * sP1 : nullptr;
    const float* p2 = (EPI == 4 || EPI == 5 || EPI == 7) ? P2 + (size_t)(bz % mP2) * sP2 : nullptr;
    const float* p3 = (EPI == 7 || EPI == 9) ? P3 + (size_t)bz * sP3 : nullptr;

    int tid  = threadIdx.x;
    int lane = tid & 31, wid = tid >> 5;
    int wm = wid & 1, wn = wid >> 1;
    int g = lane >> 2, t = lane & 3;
    int m0 = blockIdx.y * 128;
    int n0 = blockIdx.x * 128;

    int arr[4], akk[4], bkk[4], bnn[4];
    const float* aS[4];
    const float* bS[4];
    bool am[4];
#pragma unroll
    for (int i = 0; i < 4; i++) {
        int c = tid + i * 256;
        arr[i] = c >> 3; akk[i] = (c & 7) << 2;
        am[i] = (m0 + arr[i]) < M;
        int rc = am[i] ? (m0 + arr[i]) : (M - 1);
        aS[i] = A + (size_t)rc * lda + akk[i];
        bkk[i] = c >> 5; bnn[i] = (c & 31) << 2;
        bS[i] = Bm + (size_t)bkk[i] * ldb + n0 + bnn[i];
    }

    unsigned sbase = (unsigned)__cvta_generic_to_shared(smem);
    unsigned aD[4], bD[4];
#pragma unroll
    for (int i = 0; i < 4; i++) {
        aD[i] = sbase + (arr[i] * ASTR + akk[i]) * 4;
        bD[i] = sbase + (STAGES * ASZ + bkk[i] * BSTR + bnn[i]) * 4;
    }

    auto COPY = [&](int s, int k0) {
        unsigned so  = s * (ASZ * 4);
        unsigned sob = s * (BSZ * 4);
#pragma unroll
        for (int i = 0; i < 4; i++) {
            unsigned p = am[i] ? 16u : 0u;
            asm volatile("cp.async.cg.shared.global [%0], [%1], 16, %2;\n"
                         :: "r"(aD[i] + so), "l"(aS[i] + k0), "r"(p));
        }
#pragma unroll
        for (int i = 0; i < 4; i++) {
            unsigned p = (k0 + bkk[i] < KB) ? 16u : 0u;
            asm volatile("cp.async.cg.shared.global [%0], [%1], 16, %2;\n"
                         :: "r"(bD[i] + sob), "l"(bS[i] + (size_t)k0 * ldb), "r"(p));
        }
    };

    const float* aBase = sA + (wm * 64 + g) * ASTR + t;
    const float* bBase = sB + t * BSTR + wn * 32 + g;

    float acc[16][4];
#pragma unroll
    for (int i = 0; i < 16; i++)
#pragma unroll
        for (int j = 0; j < 4; j++) acc[i][j] = 0.f;

    int nk = K >> 5;

#pragma unroll
    for (int s = 0; s < STAGES - 1; s++) {
        if (s < nk) COPY(s, s << 5);
        asm volatile("cp.async.commit_group;\n");
    }

    int cur = 0, nxt = STAGES - 1;
    for (int kb = 0; kb < nk; kb++) {
        asm volatile("cp.async.wait_group %0;\n" :: "n"(STAGES - 2));
        __syncthreads();
        if (kb + STAGES - 1 < nk) COPY(nxt, (kb + STAGES - 1) << 5);
        asm volatile("cp.async.commit_group;\n");

        const float* ab = aBase + cur * ASZ;
        const float* bb = bBase + cur * BSZ;

#pragma unroll
        for (int ks = 0; ks < 4; ks++) {
            const int ko  = ks * 8;
            const int kbo = ks * (8 * BSTR);
            unsigned af[4][4], bf[4][2];
#pragma unroll
            for (int mt = 0; mt < 4; mt++) {
                const float* a = ab + mt * (16 * ASTR) + ko;
                af[mt][0] = fbits(a[0]);
                af[mt][1] = fbits(a[8 * ASTR]);
                af[mt][2] = fbits(a[4]);
                af[mt][3] = fbits(a[8 * ASTR + 4]);
            }
#pragma unroll
            for (int nt = 0; nt < 4; nt++) {
                const float* b = bb + kbo + nt * 8;
                bf[nt][0] = fbits(b[0]);
                bf[nt][1] = fbits(b[4 * BSTR]);
            }
#pragma unroll
            for (int mt = 0; mt < 4; mt++)
#pragma unroll
                for (int nt = 0; nt < 4; nt++) {
                    float* c = acc[mt * 4 + nt];
                    asm volatile(
                        "mma.sync.aligned.m16n8k8.row.col.f32.tf32.tf32.f32 "
                        "{%0,%1,%2,%3}, {%4,%5,%6,%7}, {%8,%9}, {%0,%1,%2,%3};"
                        : "+f"(c[0]), "+f"(c[1]), "+f"(c[2]), "+f"(c[3])
                        : "r"(af[mt][0]), "r"(af[mt][1]), "r"(af[mt][2]), "r"(af[mt][3]),
                          "r"(bf[nt][0]), "r"(bf[nt][1]));
                }
        }
        cur = cur + 1 == STAGES ? 0 : cur + 1;
        nxt = nxt + 1 == STAGES ? 0 : nxt + 1;
    }

    if (EPI >= 7) {
        // smem-staged transpose epilogue: all global accesses coalesced.
        asm volatile("cp.async.wait_group 0;\n");
        __syncthreads();
        float* sT = smem;
#pragma unroll
        for (int mt = 0; mt < 4; mt++)
#pragma unroll
            for (int nt = 0; nt < 4; nt++) {
                float* c = acc[mt * 4 + nt];
#pragma unroll
                for (int i = 0; i < 4; i++) {
                    int ml = wm * 64 + mt * 16 + g + (i >> 1) * 8;
                    int nl = wn * 32 + nt * 8 + 2 * t + (i & 1);
                    sT[ml * TSTR + nl] = c[i];
                }
            }
        __syncthreads();
#pragma unroll
        for (int p = 0; p < 16; p++) {
            int idx = tid + p * 256;
            int nl = idx >> 5;
            int m4 = (idx & 31) << 2;
            int n = n0 + nl;
            int m = m0 + m4;
            if (n >= N || m >= M) continue;
            float4 v4;
            v4.x = sT[(m4 + 0) * TSTR + nl];
            v4.y = sT[(m4 + 1) * TSTR + nl];
            v4.z = sT[(m4 + 2) * TSTR + nl];
            v4.w = sT[(m4 + 3) * TSTR + nl];
            if (EPI == 7 || EPI == 9) {
                const float4 q4 = *(const float4*)&p3[(size_t)n * Dm + m];
                v4.x += q4.x; v4.y += q4.y; v4.z += q4.z; v4.w += q4.w;
            }
            if (EPI == 7) {
                const float4 s4 = *(const float4*)&p1[m];
                const float4 h4 = *(const float4*)&p2[m];
                v4.x = v4.x * s4.x + h4.x;
                v4.y = v4.y * s4.y + h4.y;
                v4.z = v4.z * s4.z + h4.z;
                v4.w = v4.w * s4.w + h4.w;
            }
            *(float4*)&C[(size_t)n * ldc + m] = v4;
        }
        return;
    }

#pragma unroll
    for (int mt = 0; mt < 4; mt++)
#pragma unroll
        for (int nt = 0; nt < 4; nt++) {
            float* c = acc[mt * 4 + nt];
#pragma unroll
            for (int i = 0; i < 4; i++) {
                int m = m0 + wm * 64 + mt * 16 + g + (i >> 1) * 8;
                int n = n0 + wn * 32 + nt * 8 + 2 * t + (i & 1);
                if (m >= M || n >= N) continue;
                float v = c[i];
                if (EPI >= 1 && EPI <= 4) v += p1[n];
                if (EPI == 2) v = (v > 0.f) ? v + 1.f : expf(v);
                if (EPI == 3) {
                    float cu = v * v * v;
                    v = 0.5f * v * (1.f + tanhf(0.7978845608028654f * (v + 0.044715f * cu)));
                }
                if (EPI == 4) v += p2[(size_t)m * ldc + n];
                if (EPI == 6) {
                    v += p1[n];
                    if (bz < eluN) v = (v > 0.f) ? v + 1.f : expf(v);
                }
                if (EPI == 5) {
                    v = v * p1[m] + p2[m];
                    C[(size_t)n * ldc + m] = v;
                } else {
                    C[(size_t)m * ldc + n] = RND ? rtf(v) : v;
                }
            }
        }
}

template <int EPI, bool RND>
static void launch_gemm(cudaStream_t st,
                        const float* A, int lda, size_t sA, int mA, size_t sA2,
                        const float* B, int ldb, size_t sB, int mB, int dB,
                        float* C, int ldc, size_t sC, int mC, size_t sC2,
                        const float* P1, size_t sP1, int mP1,
                        const float* P2, size_t sP2, int mP2,
                        int M, int N, int K, int KB, int batch, int eluN = 0,
                        const float* P3 = nullptr, size_t sP3 = 0)
{
    cudaFuncSetAttribute(gemm_k<EPI, RND>,
                         cudaFuncAttributeMaxDynamicSharedMemorySize, (int)GSMEM);
    dim3 grid((N + 127) / 128, (M + 127) / 128, batch);
    gemm_k<EPI, RND><<<grid, 256, GSMEM, st>>>(A, lda, sA, mA, sA2, B, ldb, sB, mB, dB,
                                               C, ldc, sC, mC, sC2,
                                               P1, sP1, mP1, P2, sP2, mP2, P3, sP3,
                                               M, N, K, KB, eluN);
}

// ---------------------------------------------------------------------------
// Linear attention internals
// ---------------------------------------------------------------------------
__global__ void __launch_bounds__(256)
kv_part_k(const float* __restrict__ kf, const float* __restrict__ vv,
          float* __restrict__ kvp, float* __restrict__ ksp)
{
    int bh = blockIdx.x;
    int sp = blockIdx.y;
    int b = bh >> 3, h = bh & 7;
    int ts = sp * TCH, te = ts + TCH;
    const float* kbase = kf + (size_t)b * T * Dm + h * E;
    const float* vbase = vv + (size_t)b * T * Dm + h * E;
    __shared__ float ks[16][64];
    __shared__ float vs[16][64];
    int tid = threadIdx.x;
    int tx = tid & 15, ty = tid >> 4;
    float acc[4][4] = {};
    float csum = 0.f;
    for (int t0 = ts; t0 < te; t0 += 16) {
#pragma unroll
        for (int i = 0; i < 4; i++) {
            int idx = tid + i * 256;
            int rr = idx >> 6, cc = idx & 63;
            int gt = t0 + rr;
            bool ok = gt < te;
            ks[rr][cc] = ok ? kbase[(size_t)gt * Dm + cc] : 0.f;
            vs[rr][cc] = ok ? vbase[(size_t)gt * Dm + cc] : 0.f;
        }
        __syncthreads();
#pragma unroll
        for (int r = 0; r < 16; r++) {
            float a[4], bb[4];
#pragma unroll
            for (int i = 0; i < 4; i++) a[i] = ks[r][tx * 4 + i];
#pragma unroll
            for (int j = 0; j < 4; j++) bb[j] = vs[r][ty * 4 + j];
#pragma unroll
            for (int i = 0; i < 4; i++)
#pragma unroll
                for (int j = 0; j < 4; j++)
                    acc[i][j] = fmaf(a[i], bb[j], acc[i][j]);
        }
        if (tid < 64) {
#pragma unroll
            for (int r = 0; r < 16; r++) csum += ks[r][tid];
        }
        __syncthreads();
    }
    float* kvb = kvp + ((size_t)sp * 64 + bh) * E * E;
#pragma unroll
    for (int i = 0; i < 4; i++)
#pragma unroll
        for (int j = 0; j < 4; j++)
            kvb[(tx * 4 + i) * E + ty * 4 + j] = acc[i][j];
    if (tid < 64) ksp[((size_t)sp * 64 + bh) * E + tid] = csum;
}

__global__ void __launch_bounds__(256)
kv_reduce_k(const float* __restrict__ kvp, const float* __restrict__ ksp,
            float* __restrict__ kv, float* __restrict__ ksum)
{
    const int NKV = 64 * E * E;
    int i = blockIdx.x * 256 + threadIdx.x;
    if (i < NKV) {
        float s = 0.f;
#pragma unroll
        for (int sp = 0; sp < KVS; sp++) s += kvp[(size_t)sp * NKV + i];
        kv[i] = s;
    } else if (i < NKV + 64 * E) {
        int j = i - NKV;
        float s = 0.f;
#pragma unroll
        for (int sp = 0; sp < KVS; sp++) s += ksp[(size_t)sp * 64 * E + j];
        ksum[j] = s;
    }
}

__global__ void __launch_bounds__(256)
attn_o_k(const float* __restrict__ qf, const float* __restrict__ kv,
         const float* __restrict__ ksum, float* __restrict__ out)
{
    int bh = blockIdx.x;
    int b = bh >> 3, h = bh & 7;
    int t0 = blockIdx.y * 64;
    const float* qbase = qf + (size_t)b * T * Dm + h * E;
    __shared__ float qs[64][64];
    __shared__ float kvs[64][65];
    __shared__ float kss[64];
    __shared__ float zs[64];
    int tid = threadIdx.x;
    int tx = tid & 15, ty = tid >> 4;
#pragma unroll
    for (int i = 0; i < 16; i++) {
        int idx = tid + i * 256;
        int r = idx >> 6, c = idx & 63;
        kvs[r][c] = kv[(size_t)bh * E * E + idx];
        int gt = t0 + r;
        qs[r][c] = (gt < T) ? qbase[(size_t)gt * Dm + c] : 0.f;
    }
    if (tid < 64) kss[tid] = ksum[(size_t)bh * E + tid];
    __syncthreads();
    if (tid < 64) {
        float s = 0.f;
#pragma unroll
        for (int e = 0; e < 64; e++) s = fmaf(qs[tid][e], kss[e], s);
        zs[tid] = 1.f / (s + 1e-6f);
    }
    __syncthreads();
    float acc[4][4] = {};
#pragma unroll
    for (int e = 0; e < 64; e++) {
        float a[4], bb[4];
#pragma unroll
        for (int i = 0; i < 4; i++) a[i] = qs[ty * 4 + i][e];
#pragma unroll
        for (int j = 0; j < 4; j++) bb[j] = kvs[e][tx * 4 + j];
#pragma unroll
        for (int i = 0; i < 4; i++)
#pragma unroll
            for (int j = 0; j < 4; j++)
                acc[i][j] = fmaf(a[i], bb[j], acc[i][j]);
    }
#pragma unroll
    for (int i = 0; i < 4; i++) {
        int t = t0 + ty * 4 + i;
        if (t >= T) continue;
        float z = zs[ty * 4 + i];
#pragma unroll
        for (int j = 0; j < 4; j++)
            out[((size_t)b * T + t) * Dm + h * E + tx * 4 + j] = rtf(acc[i][j] * z);
    }
}

// ---------------------------------------------------------------------------
// LayerNorm over D=512
// ---------------------------------------------------------------------------
__global__ void __launch_bounds__(128)
ln_k(const float* __restrict__ x, const float* __restrict__ g,
     const float* __restrict__ bvec, float* __restrict__ outp,
     float* __restrict__ outr)
{
    int r = blockIdx.x;
    int t = threadIdx.x;
    const float4* xr = (const float4*)(x + (size_t)r * Dm);
    float4 v = xr[t];
    float s = v.x + v.y + v.z + v.w;
    float q = v.x * v.x + v.y * v.y + v.z * v.z + v.w * v.w;
#pragma unroll
    for (int o = 16; o > 0; o >>= 1) {
        s += __shfl_down_sync(0xffffffffu, s, o);
        q += __shfl_down_sync(0xffffffffu, q, o);
    }
    __shared__ float ss[4], qq[4], mv[2];
    int w = t >> 5, l = t & 31;
    if (l == 0) { ss[w] = s; qq[w] = q; }
    __syncthreads();
    if (t == 0) {
        float S = ss[0] + ss[1] + ss[2] + ss[3];
        float Q = qq[0] + qq[1] + qq[2] + qq[3];
        float m = S * (1.f / 512.f);
        float var = Q * (1.f / 512.f) - m * m;
        mv[0] = m;
        mv[1] = rsqrtf(var + 1e-5f);
    }
    __syncthreads();
    float m = mv[0], inv = mv[1];
    float4 gg = ((const float4*)g)[t];
    float4 bb = ((const float4*)bvec)[t];
    float4 o4;
    o4.x = (v.x - m) * inv * gg.x + bb.x;
    o4.y = (v.y - m) * inv * gg.y + bb.y;
    o4.z = (v.z - m) * inv * gg.z + bb.z;
    o4.w = (v.w - m) * inv * gg.w + bb.w;
    ((float4*)(outp + (size_t)r * Dm))[t] = o4;
    float4 r4;
    r4.x = rtf(o4.x); r4.y = rtf(o4.y); r4.z = rtf(o4.z); r4.w = rtf(o4.w);
    ((float4*)(outr + (size_t)r * Dm))[t] = r4;
}

// ---------------------------------------------------------------------------
// tt: cat slice0 row d col n (stride NP), rounded
// ---------------------------------------------------------------------------
__global__ void __launch_bounds__(256)
tt_k(const float* __restrict__ tout, const float* __restrict__ ttw,
     const float* __restrict__ ttb, float* __restrict__ cat)
{
    int bn = blockIdx.x;
    int b = bn / Nn, n = bn % Nn;
    __shared__ float xs[12][512];
    __shared__ float w[144];
    int tid = threadIdx.x;
    if (tid < 144) w[tid] = ttw[tid];
    for (int l = 0; l < 12; l++)
        for (int d = tid; d < 512; d += 256)
            xs[l][d] = tout[(((size_t)b * Lq + l) * Nn + n) * Dm + d];
    __syncthreads();
    for (int od = tid; od < 12 * 512; od += 256) {
        int o = od >> 9, d = od & 511;
        float s = ttb[o];
#pragma unroll
        for (int l = 0; l < 12; l++) s = fmaf(w[o * 12 + l], xs[l][d], s);
        cat[(((size_t)b * Ol + o) * CC + d) * NP + n] = rtf(s);
    }
}

// ---------------------------------------------------------------------------
// Fused rounding prep
// ---------------------------------------------------------------------------
struct PrepArgs { const float4* s[10]; };
constexpr size_t SEG0 = 0;
constexpr size_t SEG1 = MTD / 4;
constexpr size_t SEG2 = 2 * MTD / 4;
constexpr size_t SEG3 = (2 * MTD + SZ_W4) / 4;
constexpr size_t SEG4 = (2 * MTD + 2 * SZ_W4) / 4;
constexpr size_t SEG5 = (2 * MTD + 3 * SZ_W4) / 4;
constexpr size_t SEG6 = (2 * MTD + 3 * SZ_W4 + SZ_WF) / 4;
constexpr size_t SEG7 = (2 * MTD + 3 * SZ_W4 + 2 * SZ_WF) / 4;
constexpr size_t SEG8 = (2 * MTD + 3 * SZ_W4 + 3 * SZ_WF) / 4;
constexpr size_t SEG9 = (2 * MTD + 3 * SZ_W4 + 4 * SZ_WF) / 4;
constexpr size_t SEGEND = (2 * MTD + 3 * SZ_W4 + 4 * SZ_WF + SZ_WG) / 4;

__device__ __constant__ size_t dSEG[11] = {
    SEG0, SEG1, SEG2, SEG3, SEG4, SEG5, SEG6, SEG7, SEG8, SEG9, SEGEND
};
__device__ float4* const PREP_DST[10] = {
    (float4*)(g_buf + OFF_XR), (float4*)(g_buf + OFF_STR),
    (float4*)(g_buf + OFF_WEQ), (float4*)(g_buf + OFF_WDS),
    (float4*)(g_buf + OFF_WDC), (float4*)(g_buf + OFF_WE1),
    (float4*)(g_buf + OFF_WE2), (float4*)(g_buf + OFF_WD1),
    (float4*)(g_buf + OFF_WD2), (float4*)(g_buf + OFF_WG)
};

__global__ void __launch_bounds__(256)
prep_round_all(PrepArgs pa)
{
    size_t i = (size_t)blockIdx.x * 256 + threadIdx.x;
    if (i >= dSEG[10]) return;
    int seg = 0;
#pragma unroll
    for (int s = 1; s < 10; s++) seg += (i >= dSEG[s]);
    size_t off = i - dSEG[seg];
    float4 v = pa.s[seg][off];
    float4 r;
    r.x = rtf(v.x); r.y = rtf(v.y); r.z = rtf(v.z); r.w = rtf(v.w);
    PREP_DST[seg][off] = r;
}

__global__ void prep_tswT(const float* __restrict__ tsw, float* __restrict__ outT)
{
    int i = blockIdx.x * 256 + threadIdx.x;
    if (i < Nn * Dm) {
        int m = i / Dm, d = i % Dm;
        outT[(size_t)d * NP + m] = rtf(tsw[i]);
    }
}
__global__ void prep_adj(const float* __restrict__ adj, float* __restrict__ out)
{
    int i = blockIdx.x * 256 + threadIdx.x;
    if (i < NGc * Nn * Nn) {
        int s = i / (Nn * Nn);
        int r = (i / Nn) % Nn, c = i % Nn;
        out[(size_t)s * NP * NP + r * NP + c] = rtf(adj[((size_t)r * Nn + c) * NGc + s]);
    }
}
__global__ void prep_ss(const float* __restrict__ gb, const float* __restrict__ bng,
                        const float* __restrict__ bnb, float* __restrict__ sc,
                        float* __restrict__ sh)
{
    int i = blockIdx.x * 256 + threadIdx.x;
    if (i < Ol * Dm) {
        sc[i] = bng[i];
        sh[i] = gb[i] * bng[i] + bnb[i];
    }
}

// ---------------------------------------------------------------------------
// Host-side composition
// ---------------------------------------------------------------------------
constexpr int BIG = 1 << 30;

struct AScr { float *q, *k, *v, *at, *kvp, *ksp, *kv, *ksum; };

static void run_attention(cudaStream_t st,
                          const float* xqr, const float* xkvr,
                          const float* w, const float* bvec,
                          const float* res, const AScr& S, float* out)
{
    if (xqr == xkvr) {
        launch_gemm<6, false>(st, xqr, Dm, 0, 1, 0,
                              w, Dm, (size_t)Dm * Dm, 3, 1,
                              S.q, Dm, MTD, BIG, 0,
                              bvec, Dm, 3, nullptr, 0, 1,
                              MT, Dm, Dm, Dm, 3, /*eluN=*/2);
    } else {
        launch_gemm<2, false>(st, xqr, Dm, 0, 1, 0, w, Dm, 0, 1, 1,
                              S.q, Dm, 0, BIG, 0,
                              bvec, 0, 1, nullptr, 0, 1, MT, Dm, Dm, Dm, 1);
        launch_gemm<6, false>(st, xkvr, Dm, 0, 1, 0,
                              w + (size_t)Dm * Dm, Dm, (size_t)Dm * Dm, 2, 1,
                              S.k, Dm, MTD, BIG, 0,
                              bvec + Dm, Dm, 2, nullptr, 0, 1,
                              MT, Dm, Dm, Dm, 2, /*eluN=*/1);
    }
    kv_part_k<<<dim3(Bq * Hh, KVS), 256, 0, st>>>(S.k, S.v, S.kvp, S.ksp);
    kv_reduce_k<<<(64 * E * E + 64 * E + 255) / 256, 256, 0, st>>>(S.kvp, S.ksp, S.kv, S.ksum);
    attn_o_k<<<dim3(Bq * Hh, (T + 63) / 64), 256, 0, st>>>(S.q, S.kv, S.ksum, S.at);
    launch_gemm<4, false>(st, S.at, Dm, 0, 1, 0, w + 3 * (size_t)Dm * Dm, Dm, 0, 1, 1,
                          out, Dm, 0, BIG, 0,
                          bvec + 3 * Dm, 0, 1, res, 0, 1, MT, Dm, Dm, Dm, 1);
}

extern "C" void kernel_launch(void* const* d_in, const int* in_sizes, int n_in,
                              void* d_out, int out_size)
{
    const float* x    = (const float*)d_in[0];
    const float* st   = (const float*)d_in[1];
    const float* adj  = (const float*)d_in[3];
    const float* eqw  = (const float*)d_in[4];
    const float* eqb  = (const float*)d_in[5];
    const float* ew1  = (const float*)d_in[6];
    const float* eb1  = (const float*)d_in[7];
    const float* ew2  = (const float*)d_in[8];
    const float* eb2  = (const float*)d_in[9];
    const float* elng = (const float*)d_in[10];
    const float* elnb = (const float*)d_in[11];
    const float* dsw  = (const float*)d_in[12];
    const float* dsb  = (const float*)d_in[13];
    const float* dcw  = (const float*)d_in[14];
    const float* dcb  = (const float*)d_in[15];
    const float* dw1  = (const float*)d_in[16];
    const float* db1  = (const float*)d_in[17];
    const float* dw2  = (const float*)d_in[18];
    const float* db2  = (const float*)d_in[19];
    const float* dlng = (const float*)d_in[20];
    const float* dlnb = (const float*)d_in[21];
    const float* ttw  = (const float*)d_in[22];
    const float* ttb  = (const float*)d_in[23];
    const float* tsw  = (const float*)d_in[24];
    const float* tsb  = (const float*)d_in[25];
    const float* gw   = (const float*)d_in[26];
    const float* gb   = (const float*)d_in[27];
    const float* bng  = (const float*)d_in[28];
    const float* bnb  = (const float*)d_in[29];

    float* buf = nullptr;
    cudaGetSymbolAddress((void**)&buf, g_buf);
    float* dout = (float*)d_out;

    static cudaStream_t sA = nullptr, sB = nullptr;
    static cudaEvent_t evFork, evMem, evTT, evAd1, evA, evB;
    if (!sA) {
        cudaStreamCreateWithFlags(&sA, cudaStreamNonBlocking);
        cudaStreamCreateWithFlags(&sB, cudaStreamNonBlocking);
        cudaEventCreateWithFlags(&evFork, cudaEventDisableTiming);
        cudaEventCreateWithFlags(&evMem, cudaEventDisableTiming);
        cudaEventCreateWithFlags(&evTT, cudaEventDisableTiming);
        cudaEventCreateWithFlags(&evAd1, cudaEventDisableTiming);
        cudaEventCreateWithFlags(&evA, cudaEventDisableTiming);
        cudaEventCreateWithFlags(&evB, cudaEventDisableTiming);
    }

    AScr S1 { buf + OFF_Q, buf + OFF_K, buf + OFF_V, buf + OFF_ATTN,
              buf + OFF_KVP, buf + OFF_KSP, buf + OFF_KV, buf + OFF_KSUM };
    AScr S2 { buf + OFF_Q2, buf + OFF_K2, buf + OFF_V2, buf + OFF_ATTN2,
              buf + OFF_KVP2, buf + OFF_KSP2, buf + OFF_KV2, buf + OFF_KSUM2 };

    PrepArgs pa;
    pa.s[0] = (const float4*)x;   pa.s[1] = (const float4*)st;
    pa.s[2] = (const float4*)eqw; pa.s[3] = (const float4*)dsw;
    pa.s[4] = (const float4*)dcw; pa.s[5] = (const float4*)ew1;
    pa.s[6] = (const float4*)ew2; pa.s[7] = (const float4*)dw1;
    pa.s[8] = (const float4*)dw2; pa.s[9] = (const float4*)gw;
    prep_round_all<<<(int)((SEGEND + 255) / 256), 256>>>(pa);
    prep_tswT<<<(Nn * Dm + 255) / 256, 256>>>(tsw, buf + OFF_TSWT);
    prep_adj<<<(NGc * Nn * Nn + 255) / 256, 256>>>(adj, buf + OFF_ADJ);
    prep_ss<<<(Ol * Dm + 255) / 256, 256>>>(gb, bng, bnb, buf + OFF_SCALE, buf + OFF_SHIFT);

    cudaEventRecord(evFork, 0);
    cudaStreamWaitEvent(sA, evFork, 0);
    cudaStreamWaitEvent(sB, evFork, 0);

    const size_t catStride = (size_t)CC * NP;
    const size_t sliceSz = (size_t)Dm * NP;

    // ==== stream A (phase 1): encoder chain, tt, static convs, GCN chunk1 ====
    run_attention(sA, buf + OFF_XR, buf + OFF_XR, buf + OFF_WEQ, eqb, x, S1, buf + OFF_H);
    ln_k<<<MT, 128, 0, sA>>>(buf + OFF_H, elng, elnb, buf + OFF_Y, buf + OFF_YR);
    launch_gemm<3, true>(sA, buf + OFF_YR, Dm, 0, 1, 0, buf + OFF_WE1, Ff, 0, 1, 1,
                         buf + OFF_FFN, Ff, 0, BIG, 0,
                         eb1, 0, 1, nullptr, 0, 1, MT, Ff, Dm, Dm, 1);
    launch_gemm<4, false>(sA, buf + OFF_FFN, Ff, 0, 1, 0, buf + OFF_WE2, Dm, 0, 1, 1,
                          buf + OFF_H, Dm, 0, BIG, 0,
                          eb2, 0, 1, buf + OFF_Y, 0, 1, MT, Dm, Ff, Ff, 1);
    ln_k<<<MT, 128, 0, sA>>>(buf + OFF_H, elng + Dm, elnb + Dm, buf + OFF_MEM, buf + OFF_MEMR);
    cudaEventRecord(evMem, sA);

    tt_k<<<Bq * Nn, 256, 0, sA>>>(buf + OFF_MEM, ttw, ttb, buf + OFF_CAT);
    cudaEventRecord(evTT, sA);

    launch_gemm<0, true>(sA, buf + OFF_CAT, NP, catStride, Bq * Ol, 0,
                         buf + OFF_ADJ, NP, (size_t)NP * NP, NGc, Bq * Ol,
                         buf + OFF_CAT + sliceSz, NP, catStride, Bq * Ol, 2 * sliceSz,
                         nullptr, 0, 1, nullptr, 0, 1,
                         Dm, Nn, NP, NP, NGc * Bq * Ol);
    launch_gemm<0, true>(sA, buf + OFF_CAT + sliceSz, NP, catStride, Bq * Ol, 2 * sliceSz,
                         buf + OFF_ADJ, NP, (size_t)NP * NP, NGc, Bq * Ol,
                         buf + OFF_CAT + 2 * sliceSz, NP, catStride, Bq * Ol, 2 * sliceSz,
                         nullptr, 0, 1, nullptr, 0, 1,
                         Dm, Nn, NP, NP, NGc * Bq * Ol);
    // GCN chunk 1: k[0, 3584), raw partials -> scratch GS [n][m]
    launch_gemm<8, false>(sA, buf + OFF_WG, CC, (size_t)Dm * CC, Ol, 0,
                          buf + OFF_CAT, NP, catStride, BIG, 1,
                          buf + OFF_GS, Dm, SZ_GS1, BIG, 0,
                          nullptr, 0, 1, nullptr, 0, 1,
                          Dm, Nn, KSPL, KSPL, Bq * Ol);

    // ==== stream B: decoder chain, s_out2, adaptive convs ====
    run_attention(sB, buf + OFF_STR, buf + OFF_STR, buf + OFF_WDS, dsb, st, S2, buf + OFF_H2);
    ln_k<<<MT, 128, 0, sB>>>(buf + OFF_H2, dlng, dlnb, buf + OFF_Y2, buf + OFF_YR2);
    cudaStreamWaitEvent(sB, evMem, 0);
    run_attention(sB, buf + OFF_YR2, buf + OFF_MEMR, buf + OFF_WDC, dcb, buf + OFF_Y2,
                  S2, buf + OFF_H2);
    ln_k<<<MT, 128, 0, sB>>>(buf + OFF_H2, dlng + Dm, dlnb + Dm, buf + OFF_Y2, buf + OFF_YR2);
    launch_gemm<3, true>(sB, buf + OFF_YR2, Dm, 0, 1, 0, buf + OFF_WD1, Ff, 0, 1, 1,
                         buf + OFF_FFN2, Ff, 0, BIG, 0,
                         db1, 0, 1, nullptr, 0, 1, MT, Ff, Dm, Dm, 1);
    launch_gemm<4, false>(sB, buf + OFF_FFN2, Ff, 0, 1, 0, buf + OFF_WD2, Dm, 0, 1, 1,
                          buf + OFF_H2, Dm, 0, BIG, 0,
                          db2, 0, 1, buf + OFF_Y2, 0, 1, MT, Dm, Ff, Ff, 1);
    ln_k<<<MT, 128, 0, sB>>>(buf + OFF_H2, dlng + 2 * Dm, dlnb + 2 * Dm,
                             buf + OFF_SOUT, buf + OFF_SOUTR);
    if ((size_t)out_size >= 2 * MTD)
        cudaMemcpyAsync(dout + MTD, buf + OFF_SOUT, MTD * sizeof(float),
                        cudaMemcpyDeviceToDevice, sB);
    launch_gemm<1, true>(sB, buf + OFF_SOUTR, Dm, 0, 1, 0, buf + OFF_TSWT, NP, 0, 1, 1,
                         buf + OFF_S2, NP, 0, BIG, 0,
                         tsb, 0, 1, nullptr, 0, 1, MT, Nn, Dm, Dm, 1);
    cudaStreamWaitEvent(sB, evTT, 0);
    launch_gemm<0, true>(sB, buf + OFF_CAT, NP, catStride, BIG, 0,
                         buf + OFF_S2, NP, (size_t)Nn * NP, BIG, 1,
                         buf + OFF_CAT + 7 * sliceSz, NP, catStride, BIG, 0,
                         nullptr, 0, 1, nullptr, 0, 1, Dm, Nn, NP, Nn, Bq * Ol);
    cudaEventRecord(evAd1, sB);
    launch_gemm<0, true>(sB, buf + OFF_CAT + 7 * sliceSz, NP, catStride, BIG, 0,
                         buf + OFF_S2, NP, (size_t)Nn * NP, BIG, 1,
                         buf + OFF_CAT + 8 * sliceSz, NP, catStride, BIG, 0,
                         nullptr, 0, 1, nullptr, 0, 1, Dm, Nn, NP, Nn, Bq * Ol);
    cudaEventRecord(evB, sB);

    // ==== stream A (phase 2): GCN chunk7 (slice 7), overlaps adaptive conv 2
    cudaStreamWaitEvent(sA, evAd1, 0);
    launch_gemm<9, false>(sA, buf + OFF_WG + KSPL, CC, (size_t)Dm * CC, Ol, 0,
                          buf + OFF_CAT + (size_t)KSPL * NP, NP, catStride, BIG, 1,
                          buf + OFF_GS, Dm, SZ_GS1, BIG, 0,
                          nullptr, 0, 1, nullptr, 0, 1,
                          Dm, Nn, KSP2 - KSPL, KSP2 - KSPL, Bq * Ol, 0,
                          buf + OFF_GS, SZ_GS1);
    cudaEventRecord(evA, sA);

    // ---- join, then GCN chunk8: slice 8 + accumulated partials + affine
    cudaStreamWaitEvent(0, evA, 0);
    cudaStreamWaitEvent(0, evB, 0);
    launch_gemm<7, false>(0, buf + OFF_WG + KSP2, CC, (size_t)Dm * CC, Ol, 0,
                          buf + OFF_CAT + (size_t)KSP2 * NP, NP, catStride, BIG, 1,
                          dout, Dm, (size_t)Nn * Dm, BIG, 0,
                          buf + OFF_SCALE, Dm, Ol,
                          buf + OFF_SHIFT, Dm, Ol,
                          Dm, Nn, CC - KSP2, CC - KSP2, Bq * Ol, 0,
                          buf + OFF_GS, SZ_GS1);
}

// round 16
// speedup vs baseline: 1.0327x; 1.0327x over previous
#include <cuda_runtime.h>
#include <cuda_bf16.h>
#include <math.h>

// ---------------------------------------------------------------------------
// Problem constants
// ---------------------------------------------------------------------------
constexpr int Bq = 8, Lq = 12, Nn = 207, Dm = 512, Hh = 8, Ff = 2048;
constexpr int Ol = 12, NGc = 3;
constexpr int T  = Lq * Nn;          // 2484
constexpr int MT = Bq * T;           // 19872 rows
constexpr int E  = Dm / Hh;          // 64
constexpr int CC = Dm * (NGc + 1) * 2 + Dm;  // 4608
constexpr int NP = 224;              // padded N/K for graph stage (mult of 32)
constexpr int KVS = 4;
constexpr int TCH = T / KVS;         // 621
constexpr int KSPL = 3584;           // GCN k-split: slices 0-6 | 7-8

constexpr size_t MTD = (size_t)MT * Dm;

// ---- scratch set 1 (encoder chain) + shared tensors
constexpr size_t OFF_XR   = 0;
constexpr size_t OFF_STR  = 1 * MTD;
constexpr size_t OFF_Q    = 2 * MTD;
constexpr size_t OFF_K    = 3 * MTD;
constexpr size_t OFF_V    = 4 * MTD;
constexpr size_t OFF_ATTN = 5 * MTD;
constexpr size_t OFF_H    = 6 * MTD;
constexpr size_t OFF_Y    = 7 * MTD;
constexpr size_t OFF_YR   = 8 * MTD;
constexpr size_t OFF_MEM  = 9 * MTD;
constexpr size_t OFF_MEMR = 10 * MTD;
constexpr size_t OFF_SOUT = 11 * MTD;
constexpr size_t OFF_SOUTR= 12 * MTD;
constexpr size_t OFF_FFN  = 13 * MTD;                 // 4*MTD
constexpr size_t OFF_WEQ  = 17 * MTD;
constexpr size_t SZ_W4    = (size_t)4 * Dm * Dm;
constexpr size_t OFF_WDS  = OFF_WEQ + SZ_W4;
constexpr size_t OFF_WDC  = OFF_WDS + SZ_W4;
constexpr size_t OFF_WE1  = OFF_WDC + SZ_W4;
constexpr size_t SZ_WF    = (size_t)Dm * Ff;
constexpr size_t OFF_WE2  = OFF_WE1 + SZ_WF;
constexpr size_t OFF_WD1  = OFF_WE2 + SZ_WF;
constexpr size_t OFF_WD2  = OFF_WD1 + SZ_WF;
constexpr size_t OFF_WG   = OFF_WD2 + SZ_WF;
constexpr size_t SZ_WG    = (size_t)Ol * Dm * CC;
constexpr size_t OFF_TSWT = OFF_WG + SZ_WG;
constexpr size_t OFF_ADJ  = OFF_TSWT + (size_t)Dm * NP;
constexpr size_t OFF_SCALE= OFF_ADJ + (size_t)NGc * NP * NP;
constexpr size_t OFF_SHIFT= OFF_SCALE + (size_t)Ol * Dm;
constexpr size_t OFF_KVP  = OFF_SHIFT + (size_t)Ol * Dm;
constexpr size_t OFF_KSP  = OFF_KVP + (size_t)KVS * 64 * E * E;
constexpr size_t OFF_KV   = OFF_KSP + (size_t)KVS * 64 * E;
constexpr size_t OFF_KSUM = OFF_KV + (size_t)64 * E * E;
constexpr size_t OFF_S2   = OFF_KSUM + (size_t)64 * E;
constexpr size_t OFF_CAT  = OFF_S2 + (size_t)MT * NP;
// ---- scratch set 2 (decoder chain)
constexpr size_t OFF_Q2   = OFF_CAT + (size_t)Bq * Ol * CC * NP;
constexpr size_t OFF_K2   = OFF_Q2 + MTD;
constexpr size_t OFF_V2   = OFF_K2 + MTD;
constexpr size_t OFF_ATTN2= OFF_V2 + MTD;
constexpr size_t OFF_H2   = OFF_ATTN2 + MTD;
constexpr size_t OFF_Y2   = OFF_H2 + MTD;
constexpr size_t OFF_YR2  = OFF_Y2 + MTD;
constexpr size_t OFF_FFN2 = OFF_YR2 + MTD;
constexpr size_t OFF_KVP2 = OFF_FFN2 + 4 * MTD;
constexpr size_t OFF_KSP2 = OFF_KVP2 + (size_t)KVS * 64 * E * E;
constexpr size_t OFF_KV2  = OFF_KSP2 + (size_t)KVS * 64 * E;
constexpr size_t OFF_KSUM2= OFF_KV2 + (size_t)64 * E * E;
// ---- GCN partial scratch, [n][m] layout: 96 x NP x Dm
constexpr size_t OFF_GS   = OFF_KSUM2 + (size_t)64 * E;
constexpr size_t SZ_GS1   = (size_t)NP * Dm;
constexpr size_t TOTAL    = OFF_GS + (size_t)Bq * Ol * SZ_GS1 + 4096;

__device__ __align__(16) float g_buf[TOTAL];

__device__ __forceinline__ unsigned f2tf(float x) {
    unsigned r;
    asm("cvt.rna.tf32.f32 %0, %1;" : "=r"(r) : "f"(x));
    return r;
}
__device__ __forceinline__ float rtf(float x) { return __uint_as_float(f2tf(x)); }
__device__ __forceinline__ unsigned fbits(float x) { return __float_as_uint(x); }

// ---------------------------------------------------------------------------
// TF32 tensor-core batched GEMM, cp.async 3-stage pipeline, BK=32 (R11 core).
// EPI: 0 none | 1 +bias[n] | 2 +bias[n],elu+1 | 3 +bias[n],gelu(tanh)
//      4 +bias[n]+res[m,n] | 5 legacy transposed affine store
//      6 +bias[n], elu+1 only when bz < eluN
//      7 smem-transpose: v += P3[n*Dm+m]; v=v*P1[m]+P2[m]; coalesced C[n*ldc+m]
//      8 smem-transpose: raw partials, coalesced store C[n*ldc+m]
// ---------------------------------------------------------------------------
constexpr int STAGES = 3;
constexpr int BK   = 32;
constexpr int ASTR = 36;
constexpr int BSTR = 136;
constexpr int ASZ  = 128 * ASTR;
constexpr int BSZ  = BK * BSTR;
constexpr size_t GSMEM = (size_t)STAGES * (ASZ + BSZ) * 4;   // 107520 B
constexpr int TSTR = 133;

template <int EPI, bool RND>
__global__ void __launch_bounds__(256, 2)
gemm_k(const float* __restrict__ A, int lda, size_t sA_, int mA, size_t sA2,
       const float* __restrict__ Bm, int ldb, size_t sB_, int mB, int dB,
       float* __restrict__ C, int ldc, size_t sC, int mC, size_t sC2,
       const float* __restrict__ P1, size_t sP1, int mP1,
       const float* __restrict__ P2, size_t sP2, int mP2,
       const float* __restrict__ P3, size_t sP3,
       int M, int N, int K, int KB, int eluN)
{
    extern __shared__ float smem[];
    float* sA = smem;
    float* sB = smem + (size_t)STAGES * ASZ;

    int bz = blockIdx.z;
    A  += (size_t)(bz % mA) * sA_ + (size_t)(bz / mA) * sA2;
    Bm += (size_t)((bz / dB) % mB) * sB_;
    C  += (size_t)(bz % mC) * sC + (size_t)(bz / mC) * sC2;
    const float* p1 = (EPI > 0) ? P1 + (size_t)(bz % mP1) * sP1 : nullptr;
    const float* p2 = (EPI == 4 || EPI == 5 || EPI == 7) ? P2 + (size_t)(bz % mP2) * sP2 : nullptr;
    const float* p3 = (EPI == 7) ? P3 + (size_t)bz * sP3 : nullptr;

    int tid  = threadIdx.x;
    int lane = tid & 31, wid = tid >> 5;
    int wm = wid & 1, wn = wid >> 1;
    int g = lane >> 2, t = lane & 3;
    int m0 = blockIdx.y * 128;
    int n0 = blockIdx.x * 128;

    int arr[4], akk[4], bkk[4], bnn[4];
    const float* aS[4];
    const float* bS[4];
    bool am[4];
#pragma unroll
    for (int i = 0; i < 4; i++) {
        int c = tid + i * 256;
        arr[i] = c >> 3; akk[i] = (c & 7) << 2;
        am[i] = (m0 + arr[i]) < M;
        int rc = am[i] ? (m0 + arr[i]) : (M - 1);
        aS[i] = A + (size_t)rc * lda + akk[i];
        bkk[i] = c >> 5; bnn[i] = (c & 31) << 2;
        bS[i] = Bm + (size_t)bkk[i] * ldb + n0 + bnn[i];
    }

    unsigned sbase = (unsigned)__cvta_generic_to_shared(smem);
    unsigned aD[4], bD[4];
#pragma unroll
    for (int i = 0; i < 4; i++) {
        aD[i] = sbase + (arr[i] * ASTR + akk[i]) * 4;
        bD[i] = sbase + (STAGES * ASZ + bkk[i] * BSTR + bnn[i]) * 4;
    }

    auto COPY = [&](int s, int k0) {
        unsigned so  = s * (ASZ * 4);
        unsigned sob = s * (BSZ * 4);
#pragma unroll
        for (int i = 0; i < 4; i++) {
            unsigned p = am[i] ? 16u : 0u;
            asm volatile("cp.async.cg.shared.global [%0], [%1], 16, %2;\n"
                         :: "r"(aD[i] + so), "l"(aS[i] + k0), "r"(p));
        }
#pragma unroll
        for (int i = 0; i < 4; i++) {
            unsigned p = (k0 + bkk[i] < KB) ? 16u : 0u;
            asm volatile("cp.async.cg.shared.global [%0], [%1], 16, %2;\n"
                         :: "r"(bD[i] + sob), "l"(bS[i] + (size_t)k0 * ldb), "r"(p));
        }
    };

    const float* aBase = sA + (wm * 64 + g) * ASTR + t;
    const float* bBase = sB + t * BSTR + wn * 32 + g;

    float acc[16][4];
#pragma unroll
    for (int i = 0; i < 16; i++)
#pragma unroll
        for (int j = 0; j < 4; j++) acc[i][j] = 0.f;

    int nk = K >> 5;

#pragma unroll
    for (int s = 0; s < STAGES - 1; s++) {
        if (s < nk) COPY(s, s << 5);
        asm volatile("cp.async.commit_group;\n");
    }

    int cur = 0, nxt = STAGES - 1;
    for (int kb = 0; kb < nk; kb++) {
        asm volatile("cp.async.wait_group %0;\n" :: "n"(STAGES - 2));
        __syncthreads();
        if (kb + STAGES - 1 < nk) COPY(nxt, (kb + STAGES - 1) << 5);
        asm volatile("cp.async.commit_group;\n");

        const float* ab = aBase + cur * ASZ;
        const float* bb = bBase + cur * BSZ;

#pragma unroll
        for (int ks = 0; ks < 4; ks++) {
            const int ko  = ks * 8;
            const int kbo = ks * (8 * BSTR);
            unsigned af[4][4], bf[4][2];
#pragma unroll
            for (int mt = 0; mt < 4; mt++) {
                const float* a = ab + mt * (16 * ASTR) + ko;
                af[mt][0] = fbits(a[0]);
                af[mt][1] = fbits(a[8 * ASTR]);
                af[mt][2] = fbits(a[4]);
                af[mt][3] = fbits(a[8 * ASTR + 4]);
            }
#pragma unroll
            for (int nt = 0; nt < 4; nt++) {
                const float* b = bb + kbo + nt * 8;
                bf[nt][0] = fbits(b[0]);
                bf[nt][1] = fbits(b[4 * BSTR]);
            }
#pragma unroll
            for (int mt = 0; mt < 4; mt++)
#pragma unroll
                for (int nt = 0; nt < 4; nt++) {
                    float* c = acc[mt * 4 + nt];
                    asm volatile(
                        "mma.sync.aligned.m16n8k8.row.col.f32.tf32.tf32.f32 "
                        "{%0,%1,%2,%3}, {%4,%5,%6,%7}, {%8,%9}, {%0,%1,%2,%3};"
                        : "+f"(c[0]), "+f"(c[1]), "+f"(c[2]), "+f"(c[3])
                        : "r"(af[mt][0]), "r"(af[mt][1]), "r"(af[mt][2]), "r"(af[mt][3]),
                          "r"(bf[nt][0]), "r"(bf[nt][1]));
                }
        }
        cur = cur + 1 == STAGES ? 0 : cur + 1;
        nxt = nxt + 1 == STAGES ? 0 : nxt + 1;
    }

    if (EPI >= 7) {
        asm volatile("cp.async.wait_group 0;\n");
        __syncthreads();
        float* sT = smem;
#pragma unroll
        for (int mt = 0; mt < 4; mt++)
#pragma unroll
            for (int nt = 0; nt < 4; nt++) {
                float* c = acc[mt * 4 + nt];
#pragma unroll
                for (int i = 0; i < 4; i++) {
                    int ml = wm * 64 + mt * 16 + g + (i >> 1) * 8;
                    int nl = wn * 32 + nt * 8 + 2 * t + (i & 1);
                    sT[ml * TSTR + nl] = c[i];
                }
            }
        __syncthreads();
#pragma unroll
        for (int p = 0; p < 16; p++) {
            int idx = tid + p * 256;
            int nl = idx >> 5;
            int m4 = (idx & 31) << 2;
            int n = n0 + nl;
            int m = m0 + m4;
            if (n >= N || m >= M) continue;
            float4 v4;
            v4.x = sT[(m4 + 0) * TSTR + nl];
            v4.y = sT[(m4 + 1) * TSTR + nl];
            v4.z = sT[(m4 + 2) * TSTR + nl];
            v4.w = sT[(m4 + 3) * TSTR + nl];
            if (EPI == 7) {
                const float4 q4 = *(const float4*)&p3[(size_t)n * Dm + m];
                const float4 s4 = *(const float4*)&p1[m];
                const float4 h4 = *(const float4*)&p2[m];
                v4.x = (v4.x + q4.x) * s4.x + h4.x;
                v4.y = (v4.y + q4.y) * s4.y + h4.y;
                v4.z = (v4.z + q4.z) * s4.z + h4.z;
                v4.w = (v4.w + q4.w) * s4.w + h4.w;
            }
            *(float4*)&C[(size_t)n * ldc + m] = v4;
        }
        return;
    }

#pragma unroll
    for (int mt = 0; mt < 4; mt++)
#pragma unroll
        for (int nt = 0; nt < 4; nt++) {
            float* c = acc[mt * 4 + nt];
#pragma unroll
            for (int i = 0; i < 4; i++) {
                int m = m0 + wm * 64 + mt * 16 + g + (i >> 1) * 8;
                int n = n0 + wn * 32 + nt * 8 + 2 * t + (i & 1);
                if (m >= M || n >= N) continue;
                float v = c[i];
                if (EPI >= 1 && EPI <= 4) v += p1[n];
                if (EPI == 2) v = (v > 0.f) ? v + 1.f : expf(v);
                if (EPI == 3) {
                    float cu = v * v * v;
                    v = 0.5f * v * (1.f + tanhf(0.7978845608028654f * (v + 0.044715f * cu)));
                }
                if (EPI == 4) v += p2[(size_t)m * ldc + n];
                if (EPI == 6) {
                    v += p1[n];
                    if (bz < eluN) v = (v > 0.f) ? v + 1.f : expf(v);
                }
                if (EPI == 5) {
                    v = v * p1[m] + p2[m];
                    C[(size_t)n * ldc + m] = v;
                } else {
                    C[(size_t)m * ldc + n] = RND ? rtf(v) : v;
                }
            }
        }
}

template <int EPI, bool RND>
static void launch_gemm(cudaStream_t st,
                        const float* A, int lda, size_t sA, int mA, size_t sA2,
                        const float* B, int ldb, size_t sB, int mB, int dB,
                        float* C, int ldc, size_t sC, int mC, size_t sC2,
                        const float* P1, size_t sP1, int mP1,
                        const float* P2, size_t sP2, int mP2,
                        int M, int N, int K, int KB, int batch, int eluN = 0,
                        const float* P3 = nullptr, size_t sP3 = 0)
{
    cudaFuncSetAttribute(gemm_k<EPI, RND>,
                         cudaFuncAttributeMaxDynamicSharedMemorySize, (int)GSMEM);
    dim3 grid((N + 127) / 128, (M + 127) / 128, batch);
    gemm_k<EPI, RND><<<grid, 256, GSMEM, st>>>(A, lda, sA, mA, sA2, B, ldb, sB, mB, dB,
                                               C, ldc, sC, mC, sC2,
                                               P1, sP1, mP1, P2, sP2, mP2, P3, sP3,
                                               M, N, K, KB, eluN);
}

// ---------------------------------------------------------------------------
// Linear attention internals
// ---------------------------------------------------------------------------
__global__ void __launch_bounds__(256)
kv_part_k(const float* __restrict__ kf, const float* __restrict__ vv,
          float* __restrict__ kvp, float* __restrict__ ksp)
{
    int bh = blockIdx.x;
    int sp = blockIdx.y;
    int b = bh >> 3, h = bh & 7;
    int ts = sp * TCH, te = ts + TCH;
    const float* kbase = kf + (size_t)b * T * Dm + h * E;
    const float* vbase = vv + (size_t)b * T * Dm + h * E;
    __shared__ float ks[16][64];
    __shared__ float vs[16][64];
    int tid = threadIdx.x;
    int tx = tid & 15, ty = tid >> 4;
    float acc[4][4] = {};
    float csum = 0.f;
    for (int t0 = ts; t0 < te; t0 += 16) {
#pragma unroll
        for (int i = 0; i < 4; i++) {
            int idx = tid + i * 256;
            int rr = idx >> 6, cc = idx & 63;
            int gt = t0 + rr;
            bool ok = gt < te;
            ks[rr][cc] = ok ? kbase[(size_t)gt * Dm + cc] : 0.f;
            vs[rr][cc] = ok ? vbase[(size_t)gt * Dm + cc] : 0.f;
        }
        __syncthreads();
#pragma unroll
        for (int r = 0; r < 16; r++) {
            float a[4], bb[4];
#pragma unroll
            for (int i = 0; i < 4; i++) a[i] = ks[r][tx * 4 + i];
#pragma unroll
            for (int j = 0; j < 4; j++) bb[j] = vs[r][ty * 4 + j];
#pragma unroll
            for (int i = 0; i < 4; i++)
#pragma unroll
                for (int j = 0; j < 4; j++)
                    acc[i][j] = fmaf(a[i], bb[j], acc[i][j]);
        }
        if (tid < 64) {
#pragma unroll
            for (int r = 0; r < 16; r++) csum += ks[r][tid];
        }
        __syncthreads();
    }
    float* kvb = kvp + ((size_t)sp * 64 + bh) * E * E;
#pragma unroll
    for (int i = 0; i < 4; i++)
#pragma unroll
        for (int j = 0; j < 4; j++)
            kvb[(tx * 4 + i) * E + ty * 4 + j] = acc[i][j];
    if (tid < 64) ksp[((size_t)sp * 64 + bh) * E + tid] = csum;
}

__global__ void __launch_bounds__(256)
kv_reduce_k(const float* __restrict__ kvp, const float* __restrict__ ksp,
            float* __restrict__ kv, float* __restrict__ ksum)
{
    const int NKV = 64 * E * E;
    int i = blockIdx.x * 256 + threadIdx.x;
    if (i < NKV) {
        float s = 0.f;
#pragma unroll
        for (int sp = 0; sp < KVS; sp++) s += kvp[(size_t)sp * NKV + i];
        kv[i] = s;
    } else if (i < NKV + 64 * E) {
        int j = i - NKV;
        float s = 0.f;
#pragma unroll
        for (int sp = 0; sp < KVS; sp++) s += ksp[(size_t)sp * 64 * E + j];
        ksum[j] = s;
    }
}

__global__ void __launch_bounds__(256)
attn_o_k(const float* __restrict__ qf, const float* __restrict__ kv,
         const float* __restrict__ ksum, float* __restrict__ out)
{
    int bh = blockIdx.x;
    int b = bh >> 3, h = bh & 7;
    int t0 = blockIdx.y * 64;
    const float* qbase = qf + (size_t)b * T * Dm + h * E;
    __shared__ float qs[64][64];
    __shared__ float kvs[64][65];
    __shared__ float kss[64];
    __shared__ float zs[64];
    int tid = threadIdx.x;
    int tx = tid & 15, ty = tid >> 4;
#pragma unroll
    for (int i = 0; i < 16; i++) {
        int idx = tid + i * 256;
        int r = idx >> 6, c = idx & 63;
        kvs[r][c] = kv[(size_t)bh * E * E + idx];
        int gt = t0 + r;
        qs[r][c] = (gt < T) ? qbase[(size_t)gt * Dm + c] : 0.f;
    }
    if (tid < 64) kss[tid] = ksum[(size_t)bh * E + tid];
    __syncthreads();
    if (tid < 64) {
        float s = 0.f;
#pragma unroll
        for (int e = 0; e < 64; e++) s = fmaf(qs[tid][e], kss[e], s);
        zs[tid] = 1.f / (s + 1e-6f);
    }
    __syncthreads();
    float acc[4][4] = {};
#pragma unroll
    for (int e = 0; e < 64; e++) {
        float a[4], bb[4];
#pragma unroll
        for (int i = 0; i < 4; i++) a[i] = qs[ty * 4 + i][e];
#pragma unroll
        for (int j = 0; j < 4; j++) bb[j] = kvs[e][tx * 4 + j];
#pragma unroll
        for (int i = 0; i < 4; i++)
#pragma unroll
            for (int j = 0; j < 4; j++)
                acc[i][j] = fmaf(a[i], bb[j], acc[i][j]);
    }
#pragma unroll
    for (int i = 0; i < 4; i++) {
        int t = t0 + ty * 4 + i;
        if (t >= T) continue;
        float z = zs[ty * 4 + i];
#pragma unroll
        for (int j = 0; j < 4; j++)
            out[((size_t)b * T + t) * Dm + h * E + tx * 4 + j] = rtf(acc[i][j] * z);
    }
}

// ---------------------------------------------------------------------------
// LayerNorm over D=512
// ---------------------------------------------------------------------------
__global__ void __launch_bounds__(128)
ln_k(const float* __restrict__ x, const float* __restrict__ g,
     const float* __restrict__ bvec, float* __restrict__ outp,
     float* __restrict__ outr)
{
    int r = blockIdx.x;
    int t = threadIdx.x;
    const float4* xr = (const float4*)(x + (size_t)r * Dm);
    float4 v = xr[t];
    float s = v.x + v.y + v.z + v.w;
    float q = v.x * v.x + v.y * v.y + v.z * v.z + v.w * v.w;
#pragma unroll
    for (int o = 16; o > 0; o >>= 1) {
        s += __shfl_down_sync(0xffffffffu, s, o);
        q += __shfl_down_sync(0xffffffffu, q, o);
    }
    __shared__ float ss[4], qq[4], mv[2];
    int w = t >> 5, l = t & 31;
    if (l == 0) { ss[w] = s; qq[w] = q; }
    __syncthreads();
    if (t == 0) {
        float S = ss[0] + ss[1] + ss[2] + ss[3];
        float Q = qq[0] + qq[1] + qq[2] + qq[3];
        float m = S * (1.f / 512.f);
        float var = Q * (1.f / 512.f) - m * m;
        mv[0] = m;
        mv[1] = rsqrtf(var + 1e-5f);
    }
    __syncthreads();
    float m = mv[0], inv = mv[1];
    float4 gg = ((const float4*)g)[t];
    float4 bb = ((const float4*)bvec)[t];
    float4 o4;
    o4.x = (v.x - m) * inv * gg.x + bb.x;
    o4.y = (v.y - m) * inv * gg.y + bb.y;
    o4.z = (v.z - m) * inv * gg.z + bb.z;
    o4.w = (v.w - m) * inv * gg.w + bb.w;
    ((float4*)(outp + (size_t)r * Dm))[t] = o4;
    float4 r4;
    r4.x = rtf(o4.x); r4.y = rtf(o4.y); r4.z = rtf(o4.z); r4.w = rtf(o4.w);
    ((float4*)(outr + (size_t)r * Dm))[t] = r4;
}

// ---------------------------------------------------------------------------
// tt: cat slice0 row d col n (stride NP), rounded
// ---------------------------------------------------------------------------
__global__ void __launch_bounds__(256)
tt_k(const float* __restrict__ tout, const float* __restrict__ ttw,
     const float* __restrict__ ttb, float* __restrict__ cat)
{
    int bn = blockIdx.x;
    int b = bn / Nn, n = bn % Nn;
    __shared__ float xs[12][512];
    __shared__ float w[144];
    int tid = threadIdx.x;
    if (tid < 144) w[tid] = ttw[tid];
    for (int l = 0; l < 12; l++)
        for (int d = tid; d < 512; d += 256)
            xs[l][d] = tout[(((size_t)b * Lq + l) * Nn + n) * Dm + d];
    __syncthreads();
    for (int od = tid; od < 12 * 512; od += 256) {
        int o = od >> 9, d = od & 511;
        float s = ttb[o];
#pragma unroll
        for (int l = 0; l < 12; l++) s = fmaf(w[o * 12 + l], xs[l][d], s);
        cat[(((size_t)b * Ol + o) * CC + d) * NP + n] = rtf(s);
    }
}

// ---------------------------------------------------------------------------
// Prep kernels
// ---------------------------------------------------------------------------
__global__ void __launch_bounds__(256)
round4_k(const float4* __restrict__ src, float4* __restrict__ dst, size_t n4)
{
    size_t i = (size_t)blockIdx.x * 256 + threadIdx.x;
    if (i >= n4) return;
    float4 v = src[i];
    float4 r;
    r.x = rtf(v.x); r.y = rtf(v.y); r.z = rtf(v.z); r.w = rtf(v.w);
    dst[i] = r;
}

__global__ void prep_tswT(const float* __restrict__ tsw, float* __restrict__ outT)
{
    int i = blockIdx.x * 256 + threadIdx.x;
    if (i < Nn * Dm) {
        int m = i / Dm, d = i % Dm;
        outT[(size_t)d * NP + m] = rtf(tsw[i]);
    }
}
__global__ void prep_adj(const float* __restrict__ adj, float* __restrict__ out)
{
    int i = blockIdx.x * 256 + threadIdx.x;
    if (i < NGc * Nn * Nn) {
        int s = i / (Nn * Nn);
        int r = (i / Nn) % Nn, c = i % Nn;
        out[(size_t)s * NP * NP + r * NP + c] = rtf(adj[((size_t)r * Nn + c) * NGc + s]);
    }
}
__global__ void prep_ss(const float* __restrict__ gb, const float* __restrict__ bng,
                        const float* __restrict__ bnb, float* __restrict__ sc,
                        float* __restrict__ sh)
{
    int i = blockIdx.x * 256 + threadIdx.x;
    if (i < Ol * Dm) {
        sc[i] = bng[i];
        sh[i] = gb[i] * bng[i] + bnb[i];
    }
}

// ---------------------------------------------------------------------------
// Host-side composition
// ---------------------------------------------------------------------------
constexpr int BIG = 1 << 30;

struct AScr { float *q, *k, *v, *at, *kvp, *ksp, *kv, *ksum; };

static void RND4(cudaStream_t st, const float* s, float* d, size_t n)
{
    size_t n4 = n / 4;
    round4_k<<<(int)((n4 + 255) / 256), 256, 0, st>>>((const float4*)s, (float4*)d, n4);
}

static void run_attention(cudaStream_t st,
                          const float* xqr, const float* xkvr,
                          const float* w, const float* bvec,
                          const float* res, const AScr& S, float* out)
{
    if (xqr == xkvr) {
        launch_gemm<6, false>(st, xqr, Dm, 0, 1, 0,
                              w, Dm, (size_t)Dm * Dm, 3, 1,
                              S.q, Dm, MTD, BIG, 0,
                              bvec, Dm, 3, nullptr, 0, 1,
                              MT, Dm, Dm, Dm, 3, /*eluN=*/2);
    } else {
        launch_gemm<2, false>(st, xqr, Dm, 0, 1, 0, w, Dm, 0, 1, 1,
                              S.q, Dm, 0, BIG, 0,
                              bvec, 0, 1, nullptr, 0, 1, MT, Dm, Dm, Dm, 1);
        launch_gemm<6, false>(st, xkvr, Dm, 0, 1, 0,
                              w + (size_t)Dm * Dm, Dm, (size_t)Dm * Dm, 2, 1,
                              S.k, Dm, MTD, BIG, 0,
                              bvec + Dm, Dm, 2, nullptr, 0, 1,
                              MT, Dm, Dm, Dm, 2, /*eluN=*/1);
    }
    kv_part_k<<<dim3(Bq * Hh, KVS), 256, 0, st>>>(S.k, S.v, S.kvp, S.ksp);
    kv_reduce_k<<<(64 * E * E + 64 * E + 255) / 256, 256, 0, st>>>(S.kvp, S.ksp, S.kv, S.ksum);
    attn_o_k<<<dim3(Bq * Hh, (T + 63) / 64), 256, 0, st>>>(S.q, S.kv, S.ksum, S.at);
    launch_gemm<4, false>(st, S.at, Dm, 0, 1, 0, w + 3 * (size_t)Dm * Dm, Dm, 0, 1, 1,
                          out, Dm, 0, BIG, 0,
                          bvec + 3 * Dm, 0, 1, res, 0, 1, MT, Dm, Dm, Dm, 1);
}

extern "C" void kernel_launch(void* const* d_in, const int* in_sizes, int n_in,
                              void* d_out, int out_size)
{
    const float* x    = (const float*)d_in[0];
    const float* st   = (const float*)d_in[1];
    const float* adj  = (const float*)d_in[3];
    const float* eqw  = (const float*)d_in[4];
    const float* eqb  = (const float*)d_in[5];
    const float* ew1  = (const float*)d_in[6];
    const float* eb1  = (const float*)d_in[7];
    const float* ew2  = (const float*)d_in[8];
    const float* eb2  = (const float*)d_in[9];
    const float* elng = (const float*)d_in[10];
    const float* elnb = (const float*)d_in[11];
    const float* dsw  = (const float*)d_in[12];
    const float* dsb  = (const float*)d_in[13];
    const float* dcw  = (const float*)d_in[14];
    const float* dcb  = (const float*)d_in[15];
    const float* dw1  = (const float*)d_in[16];
    const float* db1  = (const float*)d_in[17];
    const float* dw2  = (const float*)d_in[18];
    const float* db2  = (const float*)d_in[19];
    const float* dlng = (const float*)d_in[20];
    const float* dlnb = (const float*)d_in[21];
    const float* ttw  = (const float*)d_in[22];
    const float* ttb  = (const float*)d_in[23];
    const float* tsw  = (const float*)d_in[24];
    const float* tsb  = (const float*)d_in[25];
    const float* gw   = (const float*)d_in[26];
    const float* gb   = (const float*)d_in[27];
    const float* bng  = (const float*)d_in[28];
    const float* bnb  = (const float*)d_in[29];

    float* buf = nullptr;
    cudaGetSymbolAddress((void**)&buf, g_buf);
    float* dout = (float*)d_out;

    static cudaStream_t sA = nullptr, sB = nullptr;
    static cudaEvent_t evFork, evPrepB, evMem, evTT, evA, evB;
    if (!sA) {
        cudaStreamCreateWithFlags(&sA, cudaStreamNonBlocking);
        cudaStreamCreateWithFlags(&sB, cudaStreamNonBlocking);
        cudaEventCreateWithFlags(&evFork, cudaEventDisableTiming);
        cudaEventCreateWithFlags(&evPrepB, cudaEventDisableTiming);
        cudaEventCreateWithFlags(&evMem, cudaEventDisableTiming);
        cudaEventCreateWithFlags(&evTT, cudaEventDisableTiming);
        cudaEventCreateWithFlags(&evA, cudaEventDisableTiming);
        cudaEventCreateWithFlags(&evB, cudaEventDisableTiming);
    }

    AScr S1 { buf + OFF_Q, buf + OFF_K, buf + OFF_V, buf + OFF_ATTN,
              buf + OFF_KVP, buf + OFF_KSP, buf + OFF_KV, buf + OFF_KSUM };
    AScr S2 { buf + OFF_Q2, buf + OFF_K2, buf + OFF_V2, buf + OFF_ATTN2,
              buf + OFF_KVP2, buf + OFF_KSP2, buf + OFF_KV2, buf + OFF_KSUM2 };

    // ---- fork immediately
    cudaEventRecord(evFork, 0);
    cudaStreamWaitEvent(sA, evFork, 0);
    cudaStreamWaitEvent(sB, evFork, 0);

    const size_t catStride = (size_t)CC * NP;
    const size_t sliceSz = (size_t)Dm * NP;

    // ==== stream B (enqueued FIRST so evPrepB is recorded before sA waits) ====
    // B-local prep + all remaining weight prep (fills B's pre-evMem slack)
    RND4(sB, st, buf + OFF_STR, MTD);
    RND4(sB, dsw, buf + OFF_WDS, SZ_W4);
    RND4(sB, dcw, buf + OFF_WDC, SZ_W4);
    RND4(sB, ew1, buf + OFF_WE1, SZ_WF);
    RND4(sB, ew2, buf + OFF_WE2, SZ_WF);
    RND4(sB, dw1, buf + OFF_WD1, SZ_WF);
    RND4(sB, dw2, buf + OFF_WD2, SZ_WF);
    RND4(sB, gw, buf + OFF_WG, SZ_WG);
    prep_tswT<<<(Nn * Dm + 255) / 256, 256, 0, sB>>>(tsw, buf + OFF_TSWT);
    prep_adj<<<(NGc * Nn * Nn + 255) / 256, 256, 0, sB>>>(adj, buf + OFF_ADJ);
    prep_ss<<<(Ol * Dm + 255) / 256, 256, 0, sB>>>(gb, bng, bnb,
                                                   buf + OFF_SCALE, buf + OFF_SHIFT);
    cudaEventRecord(evPrepB, sB);

    // ==== stream A: minimal prep (x, eqw), then encoder chain ====
    RND4(sA, x, buf + OFF_XR, MTD);
    RND4(sA, eqw, buf + OFF_WEQ, SZ_W4);
    run_attention(sA, buf + OFF_XR, buf + OFF_XR, buf + OFF_WEQ, eqb, x, S1, buf + OFF_H);
    ln_k<<<MT, 128, 0, sA>>>(buf + OFF_H, elng, elnb, buf + OFF_Y, buf + OFF_YR);
    cudaStreamWaitEvent(sA, evPrepB, 0);   // WE1/WE2/WG/ADJ ready
    launch_gemm<3, true>(sA, buf + OFF_YR, Dm, 0, 1, 0, buf + OFF_WE1, Ff, 0, 1, 1,
                         buf + OFF_FFN, Ff, 0, BIG, 0,
                         eb1, 0, 1, nullptr, 0, 1, MT, Ff, Dm, Dm, 1);
    launch_gemm<4, false>(sA, buf + OFF_FFN, Ff, 0, 1, 0, buf + OFF_WE2, Dm, 0, 1, 1,
                          buf + OFF_H, Dm, 0, BIG, 0,
                          eb2, 0, 1, buf + OFF_Y, 0, 1, MT, Dm, Ff, Ff, 1);
    ln_k<<<MT, 128, 0, sA>>>(buf + OFF_H, elng + Dm, elnb + Dm, buf + OFF_MEM, buf + OFF_MEMR);
    cudaEventRecord(evMem, sA);

    tt_k<<<Bq * Nn, 256, 0, sA>>>(buf + OFF_MEM, ttw, ttb, buf + OFF_CAT);
    cudaEventRecord(evTT, sA);

    launch_gemm<0, true>(sA, buf + OFF_CAT, NP, catStride, Bq * Ol, 0,
                         buf + OFF_ADJ, NP, (size_t)NP * NP, NGc, Bq * Ol,
                         buf + OFF_CAT + sliceSz, NP, catStride, Bq * Ol, 2 * sliceSz,
                         nullptr, 0, 1, nullptr, 0, 1,
                         Dm, Nn, NP, NP, NGc * Bq * Ol);
    launch_gemm<0, true>(sA, buf + OFF_CAT + sliceSz, NP, catStride, Bq * Ol, 2 * sliceSz,
                         buf + OFF_ADJ, NP, (size_t)NP * NP, NGc, Bq * Ol,
                         buf + OFF_CAT + 2 * sliceSz, NP, catStride, Bq * Ol, 2 * sliceSz,
                         nullptr, 0, 1, nullptr, 0, 1,
                         Dm, Nn, NP, NP, NGc * Bq * Ol);
    // GCN chunk 1: k[0, 3584), raw partials -> scratch GS [n][m]
    launch_gemm<8, false>(sA, buf + OFF_WG, CC, (size_t)Dm * CC, Ol, 0,
                          buf + OFF_CAT, NP, catStride, BIG, 1,
                          buf + OFF_GS, Dm, SZ_GS1, BIG, 0,
                          nullptr, 0, 1, nullptr, 0, 1,
                          Dm, Nn, KSPL, KSPL, Bq * Ol);
    cudaEventRecord(evA, sA);

    // ==== stream B compute chain (waits reference events recorded above) ====
    run_attention(sB, buf + OFF_STR, buf + OFF_STR, buf + OFF_WDS, dsb, st, S2, buf + OFF_H2);
    ln_k<<<MT, 128, 0, sB>>>(buf + OFF_H2, dlng, dlnb, buf + OFF_Y2, buf + OFF_YR2);
    cudaStreamWaitEvent(sB, evMem, 0);
    run_attention(sB, buf + OFF_YR2, buf + OFF_MEMR, buf + OFF_WDC, dcb, buf + OFF_Y2,
                  S2, buf + OFF_H2);
    ln_k<<<MT, 128, 0, sB>>>(buf + OFF_H2, dlng + Dm, dlnb + Dm, buf + OFF_Y2, buf + OFF_YR2);
    launch_gemm<3, true>(sB, buf + OFF_YR2, Dm, 0, 1, 0, buf + OFF_WD1, Ff, 0, 1, 1,
                         buf + OFF_FFN2, Ff, 0, BIG, 0,
                         db1, 0, 1, nullptr, 0, 1, MT, Ff, Dm, Dm, 1);
    launch_gemm<4, false>(sB, buf + OFF_FFN2, Ff, 0, 1, 0, buf + OFF_WD2, Dm, 0, 1, 1,
                          buf + OFF_H2, Dm, 0, BIG, 0,
                          db2, 0, 1, buf + OFF_Y2, 0, 1, MT, Dm, Ff, Ff, 1);
    ln_k<<<MT, 128, 0, sB>>>(buf + OFF_H2, dlng + 2 * Dm, dlnb + 2 * Dm,
                             buf + OFF_SOUT, buf + OFF_SOUTR);
    if ((size_t)out_size >= 2 * MTD)
        cudaMemcpyAsync(dout + MTD, buf + OFF_SOUT, MTD * sizeof(float),
                        cudaMemcpyDeviceToDevice, sB);
    launch_gemm<1, true>(sB, buf + OFF_SOUTR, Dm, 0, 1, 0, buf + OFF_TSWT, NP, 0, 1, 1,
                         buf + OFF_S2, NP, 0, BIG, 0,
                         tsb, 0, 1, nullptr, 0, 1, MT, Nn, Dm, Dm, 1);
    cudaStreamWaitEvent(sB, evTT, 0);
    launch_gemm<0, true>(sB, buf + OFF_CAT, NP, catStride, BIG, 0,
                         buf + OFF_S2, NP, (size_t)Nn * NP, BIG, 1,
                         buf + OFF_CAT + 7 * sliceSz, NP, catStride, BIG, 0,
                         nullptr, 0, 1, nullptr, 0, 1, Dm, Nn, NP, Nn, Bq * Ol);
    launch_gemm<0, true>(sB, buf + OFF_CAT + 7 * sliceSz, NP, catStride, BIG, 0,
                         buf + OFF_S2, NP, (size_t)Nn * NP, BIG, 1,
                         buf + OFF_CAT + 8 * sliceSz, NP, catStride, BIG, 0,
                         nullptr, 0, 1, nullptr, 0, 1, Dm, Nn, NP, Nn, Bq * Ol);
    cudaEventRecord(evB, sB);

    // ---- join, then GCN chunk 2: add partials (coalesced), affine, store
    cudaStreamWaitEvent(0, evA, 0);
    cudaStreamWaitEvent(0, evB, 0);
    launch_gemm<7, false>(0, buf + OFF_WG + KSPL, CC, (size_t)Dm * CC, Ol, 0,
                          buf + OFF_CAT + (size_t)KSPL * NP, NP, catStride, BIG, 1,
                          dout, Dm, (size_t)Nn * Dm, BIG, 0,
                          buf + OFF_SCALE, Dm, Ol,
                          buf + OFF_SHIFT, Dm, Ol,
                          Dm, Nn, CC - KSPL, CC - KSPL, Bq * Ol, 0,
                          buf + OFF_GS, SZ_GS1);
}

// round 17
// speedup vs baseline: 1.0360x; 1.0032x over previous
#include <cuda_runtime.h>
#include <cuda_bf16.h>
#include <math.h>

// ---------------------------------------------------------------------------
// Problem constants
// ---------------------------------------------------------------------------
constexpr int Bq = 8, Lq = 12, Nn = 207, Dm = 512, Hh = 8, Ff = 2048;
constexpr int Ol = 12, NGc = 3;
constexpr int T  = Lq * Nn;          // 2484
constexpr int MT = Bq * T;           // 19872 rows
constexpr int E  = Dm / Hh;          // 64
constexpr int CC = Dm * (NGc + 1) * 2 + Dm;  // 4608
constexpr int NP = 224;              // padded N/K for graph stage (mult of 32)
constexpr int KVS = 4;
constexpr int TCH = T / KVS;         // 621
constexpr int KSPL = 3584;           // GCN k-split: slices 0-6 | 7-8

constexpr size_t MTD = (size_t)MT * Dm;

// ---- scratch set 1 (encoder chain) + shared tensors
constexpr size_t OFF_XR   = 0;
constexpr size_t OFF_STR  = 1 * MTD;
constexpr size_t OFF_Q    = 2 * MTD;
constexpr size_t OFF_K    = 3 * MTD;
constexpr size_t OFF_V    = 4 * MTD;
constexpr size_t OFF_ATTN = 5 * MTD;
constexpr size_t OFF_H    = 6 * MTD;
constexpr size_t OFF_Y    = 7 * MTD;
constexpr size_t OFF_YR   = 8 * MTD;
constexpr size_t OFF_MEM  = 9 * MTD;
constexpr size_t OFF_MEMR = 10 * MTD;
constexpr size_t OFF_SOUT = 11 * MTD;
constexpr size_t OFF_SOUTR= 12 * MTD;
constexpr size_t OFF_FFN  = 13 * MTD;                 // 4*MTD
constexpr size_t OFF_WEQ  = 17 * MTD;
constexpr size_t SZ_W4    = (size_t)4 * Dm * Dm;
constexpr size_t OFF_WDS  = OFF_WEQ + SZ_W4;
constexpr size_t OFF_WDC  = OFF_WDS + SZ_W4;
constexpr size_t OFF_WE1  = OFF_WDC + SZ_W4;
constexpr size_t SZ_WF    = (size_t)Dm * Ff;
constexpr size_t OFF_WE2  = OFF_WE1 + SZ_WF;
constexpr size_t OFF_WD1  = OFF_WE2 + SZ_WF;
constexpr size_t OFF_WD2  = OFF_WD1 + SZ_WF;
constexpr size_t OFF_WG   = OFF_WD2 + SZ_WF;
constexpr size_t SZ_WG    = (size_t)Ol * Dm * CC;
constexpr size_t OFF_TSWT = OFF_WG + SZ_WG;
constexpr size_t OFF_ADJ  = OFF_TSWT + (size_t)Dm * NP;
constexpr size_t OFF_SCALE= OFF_ADJ + (size_t)NGc * NP * NP;
constexpr size_t OFF_SHIFT= OFF_SCALE + (size_t)Ol * Dm;
constexpr size_t OFF_KVP  = OFF_SHIFT + (size_t)Ol * Dm;
constexpr size_t OFF_KSP  = OFF_KVP + (size_t)KVS * 64 * E * E;
constexpr size_t OFF_KV   = OFF_KSP + (size_t)KVS * 64 * E;
constexpr size_t OFF_KSUM = OFF_KV + (size_t)64 * E * E;
constexpr size_t OFF_S2   = OFF_KSUM + (size_t)64 * E;
constexpr size_t OFF_CAT  = OFF_S2 + (size_t)MT * NP;
// ---- scratch set 2 (decoder chain)
constexpr size_t OFF_Q2   = OFF_CAT + (size_t)Bq * Ol * CC * NP;
constexpr size_t OFF_K2   = OFF_Q2 + MTD;
constexpr size_t OFF_V2   = OFF_K2 + MTD;
constexpr size_t OFF_ATTN2= OFF_V2 + MTD;
constexpr size_t OFF_H2   = OFF_ATTN2 + MTD;
constexpr size_t OFF_Y2   = OFF_H2 + MTD;
constexpr size_t OFF_YR2  = OFF_Y2 + MTD;
constexpr size_t OFF_FFN2 = OFF_YR2 + MTD;
constexpr size_t OFF_KVP2 = OFF_FFN2 + 4 * MTD;
constexpr size_t OFF_KSP2 = OFF_KVP2 + (size_t)KVS * 64 * E * E;
constexpr size_t OFF_KV2  = OFF_KSP2 + (size_t)KVS * 64 * E;
constexpr size_t OFF_KSUM2= OFF_KV2 + (size_t)64 * E * E;
// ---- GCN partial scratch, [n][m] layout: 96 x NP x Dm
constexpr size_t OFF_GS   = OFF_KSUM2 + (size_t)64 * E;
constexpr size_t SZ_GS1   = (size_t)NP * Dm;
constexpr size_t TOTAL    = OFF_GS + (size_t)Bq * Ol * SZ_GS1 + 4096;

__device__ __align__(16) float g_buf[TOTAL];

__device__ __forceinline__ unsigned f2tf(float x) {
    unsigned r;
    asm("cvt.rna.tf32.f32 %0, %1;" : "=r"(r) : "f"(x));
    return r;
}
__device__ __forceinline__ float rtf(float x) { return __uint_as_float(f2tf(x)); }
__device__ __forceinline__ unsigned fbits(float x) { return __float_as_uint(x); }

// ---------------------------------------------------------------------------
// TF32 tensor-core batched GEMM, cp.async 3-stage pipeline, BK=32 (R11 core).
// EPI: 0 none | 1 +bias[n] | 2 +bias[n],elu+1 | 3 +bias[n],gelu(tanh)
//      4 +bias[n]+res[m,n] | 5 legacy transposed affine store
//      6 +bias[n], elu+1 only when bz < eluN
//      7 smem-transpose: v += P3[n*Dm+m]; v=v*P1[m]+P2[m]; coalesced C[n*ldc+m]
//      8 smem-transpose: raw partials, coalesced store C[n*ldc+m]
// ---------------------------------------------------------------------------
constexpr int STAGES = 3;
constexpr int BK   = 32;
constexpr int ASTR = 36;
constexpr int BSTR = 136;
constexpr int ASZ  = 128 * ASTR;
constexpr int BSZ  = BK * BSTR;
constexpr size_t GSMEM = (size_t)STAGES * (ASZ + BSZ) * 4;   // 107520 B
constexpr int TSTR = 133;

template <int EPI, bool RND>
__global__ void __launch_bounds__(256, 2)
gemm_k(const float* __restrict__ A, int lda, size_t sA_, int mA, size_t sA2,
       const float* __restrict__ Bm, int ldb, size_t sB_, int mB, int dB,
       float* __restrict__ C, int ldc, size_t sC, int mC, size_t sC2,
       const float* __restrict__ P1, size_t sP1, int mP1,
       const float* __restrict__ P2, size_t sP2, int mP2,
       const float* __restrict__ P3, size_t sP3,
       int M, int N, int K, int KB, int eluN)
{
    extern __shared__ float smem[];
    float* sA = smem;
    float* sB = smem + (size_t)STAGES * ASZ;

    int bz = blockIdx.z;
    A  += (size_t)(bz % mA) * sA_ + (size_t)(bz / mA) * sA2;
    Bm += (size_t)((bz / dB) % mB) * sB_;
    C  += (size_t)(bz % mC) * sC + (size_t)(bz / mC) * sC2;
    const float* p1 = (EPI > 0) ? P1 + (size_t)(bz % mP1) * sP1 : nullptr;
    const float* p2 = (EPI == 4 || EPI == 5 || EPI == 7) ? P2 + (size_t)(bz % mP2) * sP2 : nullptr;
    const float* p3 = (EPI == 7) ? P3 + (size_t)bz * sP3 : nullptr;

    int tid  = threadIdx.x;
    int lane = tid & 31, wid = tid >> 5;
    int wm = wid & 1, wn = wid >> 1;
    int g = lane >> 2, t = lane & 3;
    int m0 = blockIdx.y * 128;
    int n0 = blockIdx.x * 128;

    int arr[4], akk[4], bkk[4], bnn[4];
    const float* aS[4];
    const float* bS[4];
    bool am[4];
#pragma unroll
    for (int i = 0; i < 4; i++) {
        int c = tid + i * 256;
        arr[i] = c >> 3; akk[i] = (c & 7) << 2;
        am[i] = (m0 + arr[i]) < M;
        int rc = am[i] ? (m0 + arr[i]) : (M - 1);
        aS[i] = A + (size_t)rc * lda + akk[i];
        bkk[i] = c >> 5; bnn[i] = (c & 31) << 2;
        bS[i] = Bm + (size_t)bkk[i] * ldb + n0 + bnn[i];
    }

    unsigned sbase = (unsigned)__cvta_generic_to_shared(smem);
    unsigned aD[4], bD[4];
#pragma unroll
    for (int i = 0; i < 4; i++) {
        aD[i] = sbase + (arr[i] * ASTR + akk[i]) * 4;
        bD[i] = sbase + (STAGES * ASZ + bkk[i] * BSTR + bnn[i]) * 4;
    }

    auto COPY = [&](int s, int k0) {
        unsigned so  = s * (ASZ * 4);
        unsigned sob = s * (BSZ * 4);
#pragma unroll
        for (int i = 0; i < 4; i++) {
            unsigned p = am[i] ? 16u : 0u;
            asm volatile("cp.async.cg.shared.global [%0], [%1], 16, %2;\n"
                         :: "r"(aD[i] + so), "l"(aS[i] + k0), "r"(p));
        }
#pragma unroll
        for (int i = 0; i < 4; i++) {
            unsigned p = (k0 + bkk[i] < KB) ? 16u : 0u;
            asm volatile("cp.async.cg.shared.global [%0], [%1], 16, %2;\n"
                         :: "r"(bD[i] + sob), "l"(bS[i] + (size_t)k0 * ldb), "r"(p));
        }
    };

    const float* aBase = sA + (wm * 64 + g) * ASTR + t;
    const float* bBase = sB + t * BSTR + wn * 32 + g;

    float acc[16][4];
#pragma unroll
    for (int i = 0; i < 16; i++)
#pragma unroll
        for (int j = 0; j < 4; j++) acc[i][j] = 0.f;

    int nk = K >> 5;

#pragma unroll
    for (int s = 0; s < STAGES - 1; s++) {
        if (s < nk) COPY(s, s << 5);
        asm volatile("cp.async.commit_group;\n");
    }

    int cur = 0, nxt = STAGES - 1;
    for (int kb = 0; kb < nk; kb++) {
        asm volatile("cp.async.wait_group %0;\n" :: "n"(STAGES - 2));
        __syncthreads();
        if (kb + STAGES - 1 < nk) COPY(nxt, (kb + STAGES - 1) << 5);
        asm volatile("cp.async.commit_group;\n");

        const float* ab = aBase + cur * ASZ;
        const float* bb = bBase + cur * BSZ;

#pragma unroll
        for (int ks = 0; ks < 4; ks++) {
            const int ko  = ks * 8;
            const int kbo = ks * (8 * BSTR);
            unsigned af[4][4], bf[4][2];
#pragma unroll
            for (int mt = 0; mt < 4; mt++) {
                const float* a = ab + mt * (16 * ASTR) + ko;
                af[mt][0] = fbits(a[0]);
                af[mt][1] = fbits(a[8 * ASTR]);
                af[mt][2] = fbits(a[4]);
                af[mt][3] = fbits(a[8 * ASTR + 4]);
            }
#pragma unroll
            for (int nt = 0; nt < 4; nt++) {
                const float* b = bb + kbo + nt * 8;
                bf[nt][0] = fbits(b[0]);
                bf[nt][1] = fbits(b[4 * BSTR]);
            }
#pragma unroll
            for (int mt = 0; mt < 4; mt++)
#pragma unroll
                for (int nt = 0; nt < 4; nt++) {
                    float* c = acc[mt * 4 + nt];
                    asm volatile(
                        "mma.sync.aligned.m16n8k8.row.col.f32.tf32.tf32.f32 "
                        "{%0,%1,%2,%3}, {%4,%5,%6,%7}, {%8,%9}, {%0,%1,%2,%3};"
                        : "+f"(c[0]), "+f"(c[1]), "+f"(c[2]), "+f"(c[3])
                        : "r"(af[mt][0]), "r"(af[mt][1]), "r"(af[mt][2]), "r"(af[mt][3]),
                          "r"(bf[nt][0]), "r"(bf[nt][1]));
                }
        }
        cur = cur + 1 == STAGES ? 0 : cur + 1;
        nxt = nxt + 1 == STAGES ? 0 : nxt + 1;
    }

    if (EPI >= 7) {
        asm volatile("cp.async.wait_group 0;\n");
        __syncthreads();
        float* sT = smem;
#pragma unroll
        for (int mt = 0; mt < 4; mt++)
#pragma unroll
            for (int nt = 0; nt < 4; nt++) {
                float* c = acc[mt * 4 + nt];
#pragma unroll
                for (int i = 0; i < 4; i++) {
                    int ml = wm * 64 + mt * 16 + g + (i >> 1) * 8;
                    int nl = wn * 32 + nt * 8 + 2 * t + (i & 1);
                    sT[ml * TSTR + nl] = c[i];
                }
            }
        __syncthreads();
#pragma unroll
        for (int p = 0; p < 16; p++) {
            int idx = tid + p * 256;
            int nl = idx >> 5;
            int m4 = (idx & 31) << 2;
            int n = n0 + nl;
            int m = m0 + m4;
            if (n >= N || m >= M) continue;
            float4 v4;
            v4.x = sT[(m4 + 0) * TSTR + nl];
            v4.y = sT[(m4 + 1) * TSTR + nl];
            v4.z = sT[(m4 + 2) * TSTR + nl];
            v4.w = sT[(m4 + 3) * TSTR + nl];
            if (EPI == 7) {
                const float4 q4 = *(const float4*)&p3[(size_t)n * Dm + m];
                const float4 s4 = *(const float4*)&p1[m];
                const float4 h4 = *(const float4*)&p2[m];
                v4.x = (v4.x + q4.x) * s4.x + h4.x;
                v4.y = (v4.y + q4.y) * s4.y + h4.y;
                v4.z = (v4.z + q4.z) * s4.z + h4.z;
                v4.w = (v4.w + q4.w) * s4.w + h4.w;
            }
            *(float4*)&C[(size_t)n * ldc + m] = v4;
        }
        return;
    }

#pragma unroll
    for (int mt = 0; mt < 4; mt++)
#pragma unroll
        for (int nt = 0; nt < 4; nt++) {
            float* c = acc[mt * 4 + nt];
#pragma unroll
            for (int i = 0; i < 4; i++) {
                int m = m0 + wm * 64 + mt * 16 + g + (i >> 1) * 8;
                int n = n0 + wn * 32 + nt * 8 + 2 * t + (i & 1);
                if (m >= M || n >= N) continue;
                float v = c[i];
                if (EPI >= 1 && EPI <= 4) v += p1[n];
                if (EPI == 2) v = (v > 0.f) ? v + 1.f : expf(v);
                if (EPI == 3) {
                    float cu = v * v * v;
                    v = 0.5f * v * (1.f + tanhf(0.7978845608028654f * (v + 0.044715f * cu)));
                }
                if (EPI == 4) v += p2[(size_t)m * ldc + n];
                if (EPI == 6) {
                    v += p1[n];
                    if (bz < eluN) v = (v > 0.f) ? v + 1.f : expf(v);
                }
                if (EPI == 5) {
                    v = v * p1[m] + p2[m];
                    C[(size_t)n * ldc + m] = v;
                } else {
                    C[(size_t)m * ldc + n] = RND ? rtf(v) : v;
                }
            }
        }
}

template <int EPI, bool RND>
static void launch_gemm(cudaStream_t st,
                        const float* A, int lda, size_t sA, int mA, size_t sA2,
                        const float* B, int ldb, size_t sB, int mB, int dB,
                        float* C, int ldc, size_t sC, int mC, size_t sC2,
                        const float* P1, size_t sP1, int mP1,
                        const float* P2, size_t sP2, int mP2,
                        int M, int N, int K, int KB, int batch, int eluN = 0,
                        const float* P3 = nullptr, size_t sP3 = 0)
{
    cudaFuncSetAttribute(gemm_k<EPI, RND>,
                         cudaFuncAttributeMaxDynamicSharedMemorySize, (int)GSMEM);
    dim3 grid((N + 127) / 128, (M + 127) / 128, batch);
    gemm_k<EPI, RND><<<grid, 256, GSMEM, st>>>(A, lda, sA, mA, sA2, B, ldb, sB, mB, dB,
                                               C, ldc, sC, mC, sC2,
                                               P1, sP1, mP1, P2, sP2, mP2, P3, sP3,
                                               M, N, K, KB, eluN);
}

// ---------------------------------------------------------------------------
// Linear attention internals
// ---------------------------------------------------------------------------
__global__ void __launch_bounds__(256)
kv_part_k(const float* __restrict__ kf, const float* __restrict__ vv,
          float* __restrict__ kvp, float* __restrict__ ksp)
{
    int bh = blockIdx.x;
    int sp = blockIdx.y;
    int b = bh >> 3, h = bh & 7;
    int ts = sp * TCH, te = ts + TCH;
    const float* kbase = kf + (size_t)b * T * Dm + h * E;
    const float* vbase = vv + (size_t)b * T * Dm + h * E;
    __shared__ float ks[16][64];
    __shared__ float vs[16][64];
    int tid = threadIdx.x;
    int tx = tid & 15, ty = tid >> 4;
    float acc[4][4] = {};
    float csum = 0.f;
    for (int t0 = ts; t0 < te; t0 += 16) {
#pragma unroll
        for (int i = 0; i < 4; i++) {
            int idx = tid + i * 256;
            int rr = idx >> 6, cc = idx & 63;
            int gt = t0 + rr;
            bool ok = gt < te;
            ks[rr][cc] = ok ? kbase[(size_t)gt * Dm + cc] : 0.f;
            vs[rr][cc] = ok ? vbase[(size_t)gt * Dm + cc] : 0.f;
        }
        __syncthreads();
#pragma unroll
        for (int r = 0; r < 16; r++) {
            float a[4], bb[4];
#pragma unroll
            for (int i = 0; i < 4; i++) a[i] = ks[r][tx * 4 + i];
#pragma unroll
            for (int j = 0; j < 4; j++) bb[j] = vs[r][ty * 4 + j];
#pragma unroll
            for (int i = 0; i < 4; i++)
#pragma unroll
                for (int j = 0; j < 4; j++)
                    acc[i][j] = fmaf(a[i], bb[j], acc[i][j]);
        }
        if (tid < 64) {
#pragma unroll
            for (int r = 0; r < 16; r++) csum += ks[r][tid];
        }
        __syncthreads();
    }
    float* kvb = kvp + ((size_t)sp * 64 + bh) * E * E;
#pragma unroll
    for (int i = 0; i < 4; i++)
#pragma unroll
        for (int j = 0; j < 4; j++)
            kvb[(tx * 4 + i) * E + ty * 4 + j] = acc[i][j];
    if (tid < 64) ksp[((size_t)sp * 64 + bh) * E + tid] = csum;
}

__global__ void __launch_bounds__(256)
kv_reduce_k(const float* __restrict__ kvp, const float* __restrict__ ksp,
            float* __restrict__ kv, float* __restrict__ ksum)
{
    const int NKV = 64 * E * E;
    int i = blockIdx.x * 256 + threadIdx.x;
    if (i < NKV) {
        float s = 0.f;
#pragma unroll
        for (int sp = 0; sp < KVS; sp++) s += kvp[(size_t)sp * NKV + i];
        kv[i] = s;
    } else if (i < NKV + 64 * E) {
        int j = i - NKV;
        float s = 0.f;
#pragma unroll
        for (int sp = 0; sp < KVS; sp++) s += ksp[(size_t)sp * 64 * E + j];
        ksum[j] = s;
    }
}

__global__ void __launch_bounds__(256)
attn_o_k(const float* __restrict__ qf, const float* __restrict__ kv,
         const float* __restrict__ ksum, float* __restrict__ out)
{
    int bh = blockIdx.x;
    int b = bh >> 3, h = bh & 7;
    int t0 = blockIdx.y * 64;
    const float* qbase = qf + (size_t)b * T * Dm + h * E;
    __shared__ float qs[64][64];
    __shared__ float kvs[64][65];
    __shared__ float kss[64];
    __shared__ float zs[64];
    int tid = threadIdx.x;
    int tx = tid & 15, ty = tid >> 4;
#pragma unroll
    for (int i = 0; i < 16; i++) {
        int idx = tid + i * 256;
        int r = idx >> 6, c = idx & 63;
        kvs[r][c] = kv[(size_t)bh * E * E + idx];
        int gt = t0 + r;
        qs[r][c] = (gt < T) ? qbase[(size_t)gt * Dm + c] : 0.f;
    }
    if (tid < 64) kss[tid] = ksum[(size_t)bh * E + tid];
    __syncthreads();
    if (tid < 64) {
        float s = 0.f;
#pragma unroll
        for (int e = 0; e < 64; e++) s = fmaf(qs[tid][e], kss[e], s);
        zs[tid] = 1.f / (s + 1e-6f);
    }
    __syncthreads();
    float acc[4][4] = {};
#pragma unroll
    for (int e = 0; e < 64; e++) {
        float a[4], bb[4];
#pragma unroll
        for (int i = 0; i < 4; i++) a[i] = qs[ty * 4 + i][e];
#pragma unroll
        for (int j = 0; j < 4; j++) bb[j] = kvs[e][tx * 4 + j];
#pragma unroll
        for (int i = 0; i < 4; i++)
#pragma unroll
            for (int j = 0; j < 4; j++)
                acc[i][j] = fmaf(a[i], bb[j], acc[i][j]);
    }
#pragma unroll
    for (int i = 0; i < 4; i++) {
        int t = t0 + ty * 4 + i;
        if (t >= T) continue;
        float z = zs[ty * 4 + i];
#pragma unroll
        for (int j = 0; j < 4; j++)
            out[((size_t)b * T + t) * Dm + h * E + tx * 4 + j] = rtf(acc[i][j] * z);
    }
}

// ---------------------------------------------------------------------------
// LayerNorm over D=512
// ---------------------------------------------------------------------------
__global__ void __launch_bounds__(128)
ln_k(const float* __restrict__ x, const float* __restrict__ g,
     const float* __restrict__ bvec, float* __restrict__ outp,
     float* __restrict__ outr)
{
    int r = blockIdx.x;
    int t = threadIdx.x;
    const float4* xr = (const float4*)(x + (size_t)r * Dm);
    float4 v = xr[t];
    float s = v.x + v.y + v.z + v.w;
    float q = v.x * v.x + v.y * v.y + v.z * v.z + v.w * v.w;
#pragma unroll
    for (int o = 16; o > 0; o >>= 1) {
        s += __shfl_down_sync(0xffffffffu, s, o);
        q += __shfl_down_sync(0xffffffffu, q, o);
    }
    __shared__ float ss[4], qq[4], mv[2];
    int w = t >> 5, l = t & 31;
    if (l == 0) { ss[w] = s; qq[w] = q; }
    __syncthreads();
    if (t == 0) {
        float S = ss[0] + ss[1] + ss[2] + ss[3];
        float Q = qq[0] + qq[1] + qq[2] + qq[3];
        float m = S * (1.f / 512.f);
        float var = Q * (1.f / 512.f) - m * m;
        mv[0] = m;
        mv[1] = rsqrtf(var + 1e-5f);
    }
    __syncthreads();
    float m = mv[0], inv = mv[1];
    float4 gg = ((const float4*)g)[t];
    float4 bb = ((const float4*)bvec)[t];
    float4 o4;
    o4.x = (v.x - m) * inv * gg.x + bb.x;
    o4.y = (v.y - m) * inv * gg.y + bb.y;
    o4.z = (v.z - m) * inv * gg.z + bb.z;
    o4.w = (v.w - m) * inv * gg.w + bb.w;
    ((float4*)(outp + (size_t)r * Dm))[t] = o4;
    float4 r4;
    r4.x = rtf(o4.x); r4.y = rtf(o4.y); r4.z = rtf(o4.z); r4.w = rtf(o4.w);
    ((float4*)(outr + (size_t)r * Dm))[t] = r4;
}

// ---------------------------------------------------------------------------
// tt: cat slice0 row d col n (stride NP), rounded
// ---------------------------------------------------------------------------
__global__ void __launch_bounds__(256)
tt_k(const float* __restrict__ tout, const float* __restrict__ ttw,
     const float* __restrict__ ttb, float* __restrict__ cat)
{
    int bn = blockIdx.x;
    int b = bn / Nn, n = bn % Nn;
    __shared__ float xs[12][512];
    __shared__ float w[144];
    int tid = threadIdx.x;
    if (tid < 144) w[tid] = ttw[tid];
    for (int l = 0; l < 12; l++)
        for (int d = tid; d < 512; d += 256)
            xs[l][d] = tout[(((size_t)b * Lq + l) * Nn + n) * Dm + d];
    __syncthreads();
    for (int od = tid; od < 12 * 512; od += 256) {
        int o = od >> 9, d = od & 511;
        float s = ttb[o];
#pragma unroll
        for (int l = 0; l < 12; l++) s = fmaf(w[o * 12 + l], xs[l][d], s);
        cat[(((size_t)b * Ol + o) * CC + d) * NP + n] = rtf(s);
    }
}

// ---------------------------------------------------------------------------
// Prep kernels
// ---------------------------------------------------------------------------
__global__ void __launch_bounds__(256)
round4_k(const float4* __restrict__ src, float4* __restrict__ dst, size_t n4)
{
    size_t i = (size_t)blockIdx.x * 256 + threadIdx.x;
    if (i >= n4) return;
    float4 v = src[i];
    float4 r;
    r.x = rtf(v.x); r.y = rtf(v.y); r.z = rtf(v.z); r.w = rtf(v.w);
    dst[i] = r;
}

__global__ void prep_tswT(const float* __restrict__ tsw, float* __restrict__ outT)
{
    int i = blockIdx.x * 256 + threadIdx.x;
    if (i < Nn * Dm) {
        int m = i / Dm, d = i % Dm;
        outT[(size_t)d * NP + m] = rtf(tsw[i]);
    }
}
__global__ void prep_adj(const float* __restrict__ adj, float* __restrict__ out)
{
    int i = blockIdx.x * 256 + threadIdx.x;
    if (i < NGc * Nn * Nn) {
        int s = i / (Nn * Nn);
        int r = (i / Nn) % Nn, c = i % Nn;
        out[(size_t)s * NP * NP + r * NP + c] = rtf(adj[((size_t)r * Nn + c) * NGc + s]);
    }
}
__global__ void prep_ss(const float* __restrict__ gb, const float* __restrict__ bng,
                        const float* __restrict__ bnb, float* __restrict__ sc,
                        float* __restrict__ sh)
{
    int i = blockIdx.x * 256 + threadIdx.x;
    if (i < Ol * Dm) {
        sc[i] = bng[i];
        sh[i] = gb[i] * bng[i] + bnb[i];
    }
}

// ---------------------------------------------------------------------------
// Host-side composition
// ---------------------------------------------------------------------------
constexpr int BIG = 1 << 30;

struct AScr { float *q, *k, *v, *at, *kvp, *ksp, *kv, *ksum; };

static void RND4(cudaStream_t st, const float* s, float* d, size_t n)
{
    size_t n4 = n / 4;
    round4_k<<<(int)((n4 + 255) / 256), 256, 0, st>>>((const float4*)s, (float4*)d, n4);
}

static void run_attention(cudaStream_t st,
                          const float* xqr, const float* xkvr,
                          const float* w, const float* bvec,
                          const float* res, const AScr& S, float* out)
{
    if (xqr == xkvr) {
        launch_gemm<6, false>(st, xqr, Dm, 0, 1, 0,
                              w, Dm, (size_t)Dm * Dm, 3, 1,
                              S.q, Dm, MTD, BIG, 0,
                              bvec, Dm, 3, nullptr, 0, 1,
                              MT, Dm, Dm, Dm, 3, /*eluN=*/2);
    } else {
        launch_gemm<2, false>(st, xqr, Dm, 0, 1, 0, w, Dm, 0, 1, 1,
                              S.q, Dm, 0, BIG, 0,
                              bvec, 0, 1, nullptr, 0, 1, MT, Dm, Dm, Dm, 1);
        launch_gemm<6, false>(st, xkvr, Dm, 0, 1, 0,
                              w + (size_t)Dm * Dm, Dm, (size_t)Dm * Dm, 2, 1,
                              S.k, Dm, MTD, BIG, 0,
                              bvec + Dm, Dm, 2, nullptr, 0, 1,
                              MT, Dm, Dm, Dm, 2, /*eluN=*/1);
    }
    kv_part_k<<<dim3(Bq * Hh, KVS), 256, 0, st>>>(S.k, S.v, S.kvp, S.ksp);
    kv_reduce_k<<<(64 * E * E + 64 * E + 255) / 256, 256, 0, st>>>(S.kvp, S.ksp, S.kv, S.ksum);
    attn_o_k<<<dim3(Bq * Hh, (T + 63) / 64), 256, 0, st>>>(S.q, S.kv, S.ksum, S.at);
    launch_gemm<4, false>(st, S.at, Dm, 0, 1, 0, w + 3 * (size_t)Dm * Dm, Dm, 0, 1, 1,
                          out, Dm, 0, BIG, 0,
                          bvec + 3 * Dm, 0, 1, res, 0, 1, MT, Dm, Dm, Dm, 1);
}

extern "C" void kernel_launch(void* const* d_in, const int* in_sizes, int n_in,
                              void* d_out, int out_size)
{
    const float* x    = (const float*)d_in[0];
    const float* st   = (const float*)d_in[1];
    const float* adj  = (const float*)d_in[3];
    const float* eqw  = (const float*)d_in[4];
    const float* eqb  = (const float*)d_in[5];
    const float* ew1  = (const float*)d_in[6];
    const float* eb1  = (const float*)d_in[7];
    const float* ew2  = (const float*)d_in[8];
    const float* eb2  = (const float*)d_in[9];
    const float* elng = (const float*)d_in[10];
    const float* elnb = (const float*)d_in[11];
    const float* dsw  = (const float*)d_in[12];
    const float* dsb  = (const float*)d_in[13];
    const float* dcw  = (const float*)d_in[14];
    const float* dcb  = (const float*)d_in[15];
    const float* dw1  = (const float*)d_in[16];
    const float* db1  = (const float*)d_in[17];
    const float* dw2  = (const float*)d_in[18];
    const float* db2  = (const float*)d_in[19];
    const float* dlng = (const float*)d_in[20];
    const float* dlnb = (const float*)d_in[21];
    const float* ttw  = (const float*)d_in[22];
    const float* ttb  = (const float*)d_in[23];
    const float* tsw  = (const float*)d_in[24];
    const float* tsb  = (const float*)d_in[25];
    const float* gw   = (const float*)d_in[26];
    const float* gb   = (const float*)d_in[27];
    const float* bng  = (const float*)d_in[28];
    const float* bnb  = (const float*)d_in[29];

    float* buf = nullptr;
    cudaGetSymbolAddress((void**)&buf, g_buf);
    float* dout = (float*)d_out;

    static cudaStream_t sA = nullptr, sB = nullptr;
    static cudaEvent_t evFork, evPrepB, evMem, evTT, evA, evB;
    if (!sA) {
        cudaStreamCreateWithFlags(&sA, cudaStreamNonBlocking);
        cudaStreamCreateWithFlags(&sB, cudaStreamNonBlocking);
        cudaEventCreateWithFlags(&evFork, cudaEventDisableTiming);
        cudaEventCreateWithFlags(&evPrepB, cudaEventDisableTiming);
        cudaEventCreateWithFlags(&evMem, cudaEventDisableTiming);
        cudaEventCreateWithFlags(&evTT, cudaEventDisableTiming);
        cudaEventCreateWithFlags(&evA, cudaEventDisableTiming);
        cudaEventCreateWithFlags(&evB, cudaEventDisableTiming);
    }

    AScr S1 { buf + OFF_Q, buf + OFF_K, buf + OFF_V, buf + OFF_ATTN,
              buf + OFF_KVP, buf + OFF_KSP, buf + OFF_KV, buf + OFF_KSUM };
    AScr S2 { buf + OFF_Q2, buf + OFF_K2, buf + OFF_V2, buf + OFF_ATTN2,
              buf + OFF_KVP2, buf + OFF_KSP2, buf + OFF_KV2, buf + OFF_KSUM2 };

    // ---- fork immediately
    cudaEventRecord(evFork, 0);
    cudaStreamWaitEvent(sA, evFork, 0);
    cudaStreamWaitEvent(sB, evFork, 0);

    const size_t catStride = (size_t)CC * NP;
    const size_t sliceSz = (size_t)Dm * NP;

    // ==== stream B (enqueued FIRST so evPrepB is recorded before sA waits) ====
    // B-local prep + all remaining weight prep (fills B's pre-evMem slack)
    RND4(sB, st, buf + OFF_STR, MTD);
    RND4(sB, dsw, buf + OFF_WDS, SZ_W4);
    RND4(sB, dcw, buf + OFF_WDC, SZ_W4);
    RND4(sB, ew1, buf + OFF_WE1, SZ_WF);
    RND4(sB, ew2, buf + OFF_WE2, SZ_WF);
    RND4(sB, dw1, buf + OFF_WD1, SZ_WF);
    RND4(sB, dw2, buf + OFF_WD2, SZ_WF);
    RND4(sB, gw, buf + OFF_WG, SZ_WG);
    prep_tswT<<<(Nn * Dm + 255) / 256, 256, 0, sB>>>(tsw, buf + OFF_TSWT);
    prep_adj<<<(NGc * Nn * Nn + 255) / 256, 256, 0, sB>>>(adj, buf + OFF_ADJ);
    prep_ss<<<(Ol * Dm + 255) / 256, 256, 0, sB>>>(gb, bng, bnb,
                                                   buf + OFF_SCALE, buf + OFF_SHIFT);
    cudaEventRecord(evPrepB, sB);

    // ==== stream A: minimal prep (x, eqw), then encoder chain ====
    RND4(sA, x, buf + OFF_XR, MTD);
    RND4(sA, eqw, buf + OFF_WEQ, SZ_W4);
    run_attention(sA, buf + OFF_XR, buf + OFF_XR, buf + OFF_WEQ, eqb, x, S1, buf + OFF_H);
    ln_k<<<MT, 128, 0, sA>>>(buf + OFF_H, elng, elnb, buf + OFF_Y, buf + OFF_YR);
    cudaStreamWaitEvent(sA, evPrepB, 0);   // WE1/WE2/WG/ADJ ready
    launch_gemm<3, true>(sA, buf + OFF_YR, Dm, 0, 1, 0, buf + OFF_WE1, Ff, 0, 1, 1,
                         buf + OFF_FFN, Ff, 0, BIG, 0,
                         eb1, 0, 1, nullptr, 0, 1, MT, Ff, Dm, Dm, 1);
    launch_gemm<4, false>(sA, buf + OFF_FFN, Ff, 0, 1, 0, buf + OFF_WE2, Dm, 0, 1, 1,
                          buf + OFF_H, Dm, 0, BIG, 0,
                          eb2, 0, 1, buf + OFF_Y, 0, 1, MT, Dm, Ff, Ff, 1);
    ln_k<<<MT, 128, 0, sA>>>(buf + OFF_H, elng + Dm, elnb + Dm, buf + OFF_MEM, buf + OFF_MEMR);
    cudaEventRecord(evMem, sA);

    tt_k<<<Bq * Nn, 256, 0, sA>>>(buf + OFF_MEM, ttw, ttb, buf + OFF_CAT);
    cudaEventRecord(evTT, sA);

    launch_gemm<0, true>(sA, buf + OFF_CAT, NP, catStride, Bq * Ol, 0,
                         buf + OFF_ADJ, NP, (size_t)NP * NP, NGc, Bq * Ol,
                         buf + OFF_CAT + sliceSz, NP, catStride, Bq * Ol, 2 * sliceSz,
                         nullptr, 0, 1, nullptr, 0, 1,
                         Dm, Nn, NP, NP, NGc * Bq * Ol);
    launch_gemm<0, true>(sA, buf + OFF_CAT + sliceSz, NP, catStride, Bq * Ol, 2 * sliceSz,
                         buf + OFF_ADJ, NP, (size_t)NP * NP, NGc, Bq * Ol,
                         buf + OFF_CAT + 2 * sliceSz, NP, catStride, Bq * Ol, 2 * sliceSz,
                         nullptr, 0, 1, nullptr, 0, 1,
                         Dm, Nn, NP, NP, NGc * Bq * Ol);
    // GCN chunk 1: k[0, 3584), raw partials -> scratch GS [n][m]
    launch_gemm<8, false>(sA, buf + OFF_WG, CC, (size_t)Dm * CC, Ol, 0,
                          buf + OFF_CAT, NP, catStride, BIG, 1,
                          buf + OFF_GS, Dm, SZ_GS1, BIG, 0,
                          nullptr, 0, 1, nullptr, 0, 1,
                          Dm, Nn, KSPL, KSPL, Bq * Ol);
    cudaEventRecord(evA, sA);

    // ==== stream B compute chain (waits reference events recorded above) ====
    run_attention(sB, buf + OFF_STR, buf + OFF_STR, buf + OFF_WDS, dsb, st, S2, buf + OFF_H2);
    ln_k<<<MT, 128, 0, sB>>>(buf + OFF_H2, dlng, dlnb, buf + OFF_Y2, buf + OFF_YR2);
    cudaStreamWaitEvent(sB, evMem, 0);
    run_attention(sB, buf + OFF_YR2, buf + OFF_MEMR, buf + OFF_WDC, dcb, buf + OFF_Y2,
                  S2, buf + OFF_H2);
    ln_k<<<MT, 128, 0, sB>>>(buf + OFF_H2, dlng + Dm, dlnb + Dm, buf + OFF_Y2, buf + OFF_YR2);
    launch_gemm<3, true>(sB, buf + OFF_YR2, Dm, 0, 1, 0, buf + OFF_WD1, Ff, 0, 1, 1,
                         buf + OFF_FFN2, Ff, 0, BIG, 0,
                         db1, 0, 1, nullptr, 0, 1, MT, Ff, Dm, Dm, 1);
    launch_gemm<4, false>(sB, buf + OFF_FFN2, Ff, 0, 1, 0, buf + OFF_WD2, Dm, 0, 1, 1,
                          buf + OFF_H2, Dm, 0, BIG, 0,
                          db2, 0, 1, buf + OFF_Y2, 0, 1, MT, Dm, Ff, Ff, 1);
    ln_k<<<MT, 128, 0, sB>>>(buf + OFF_H2, dlng + 2 * Dm, dlnb + 2 * Dm,
                             buf + OFF_SOUT, buf + OFF_SOUTR);
    if ((size_t)out_size >= 2 * MTD)
        cudaMemcpyAsync(dout + MTD, buf + OFF_SOUT, MTD * sizeof(float),
                        cudaMemcpyDeviceToDevice, sB);
    launch_gemm<1, true>(sB, buf + OFF_SOUTR, Dm, 0, 1, 0, buf + OFF_TSWT, NP, 0, 1, 1,
                         buf + OFF_S2, NP, 0, BIG, 0,
                         tsb, 0, 1, nullptr, 0, 1, MT, Nn, Dm, Dm, 1);
    cudaStreamWaitEvent(sB, evTT, 0);
    launch_gemm<0, true>(sB, buf + OFF_CAT, NP, catStride, BIG, 0,
                         buf + OFF_S2, NP, (size_t)Nn * NP, BIG, 1,
                         buf + OFF_CAT + 7 * sliceSz, NP, catStride, BIG, 0,
                         nullptr, 0, 1, nullptr, 0, 1, Dm, Nn, NP, Nn, Bq * Ol);
    launch_gemm<0, true>(sB, buf + OFF_CAT + 7 * sliceSz, NP, catStride, BIG, 0,
                         buf + OFF_S2, NP, (size_t)Nn * NP, BIG, 1,
                         buf + OFF_CAT + 8 * sliceSz, NP, catStride, BIG, 0,
                         nullptr, 0, 1, nullptr, 0, 1, Dm, Nn, NP, Nn, Bq * Ol);
    cudaEventRecord(evB, sB);

    // ---- join, then GCN chunk 2: add partials (coalesced), affine, store
    cudaStreamWaitEvent(0, evA, 0);
    cudaStreamWaitEvent(0, evB, 0);
    launch_gemm<7, false>(0, buf + OFF_WG + KSPL, CC, (size_t)Dm * CC, Ol, 0,
                          buf + OFF_CAT + (size_t)KSPL * NP, NP, catStride, BIG, 1,
                          dout, Dm, (size_t)Nn * Dm, BIG, 0,
                          buf + OFF_SCALE, Dm, Ol,
                          buf + OFF_SHIFT, Dm, Ol,
                          Dm, Nn, CC - KSPL, CC - KSPL, Bq * Ol, 0,
                          buf + OFF_GS, SZ_GS1);
}